// round 9
// baseline (speedup 1.0000x reference)
#include <cuda_runtime.h>
#include <math.h>
#include <float.h>

// Accurate libdevice math (same routines XLA GPU lowers f32 exp/log to).
extern "C" __device__ float __nv_expf(float);
extern "C" __device__ float __nv_logf(float);

// B=64, T=500 -> 32000 (b,t) rows; NLOGIT=13, TR=5, P=6 pairs.
// pred  : (64,500,13,5,6) f32 -> 390 floats per (b,t)
// target: (64,500,5,5,13) f32 -> 325 floats per (b,t)
// mic_locs: (4,3) f32 ; out: [loss, acc] f32
//
// 256 threads = 8 warps, one (b,t) row per warp.
// Perm-argmin: 6 groups of 5 lanes; group g owns mic-pair g; lane lig in a
// group owns first-digit p0 = lig (pe block [24*lig, 24*lig+24), ascending).

#define NBT    32000
#define WPB    8
#define NBLK   (NBT / WPB)   // 4000
#define NBUCK  32

__device__ double             g_bl[NBUCK];   // zero-init; last block re-zeroes
__device__ unsigned long long g_bc[NBUCK];
__device__ unsigned long long g_bn[NBUCK];
__device__ unsigned           g_cnt;         // wraps to 0 every full launch

// Remove nibble index i from a packed ascending-nibble set.
__device__ __forceinline__ unsigned nib_remove(unsigned r, int i) {
    unsigned mask = (1u << (4 * i)) - 1u;
    return (r & mask) | ((r >> 4) & ~mask);
}

// Lexicographic (itertools) perm index -> packed 4-bit digits (for acc step).
__device__ __forceinline__ unsigned perm_digits(int p) {
    int avail[5] = {0, 1, 2, 3, 4};
    const int fact[4] = {24, 6, 2, 1};
    unsigned pk = 0;
#pragma unroll
    for (int i = 0; i < 4; i++) {
        int d = p / fact[i];
        p -= d * fact[i];
        pk |= (unsigned)avail[d] << (4 * i);
#pragma unroll
        for (int j = 0; j < 4; j++)
            if (j >= d) avail[j] = avail[j + 1];
    }
    pk |= (unsigned)avail[0] << 16;
    return pk;
}

__global__ __launch_bounds__(256, 8) void tdoa_main(
    const float* __restrict__ pred,
    const float* __restrict__ target,
    const float* __restrict__ mics,
    float* __restrict__ out, int nout)
{
    __shared__ __align__(16) float s_pred[WPB][390];  // cl*30 + track*6 + pair
    // s_tgt (325 f) and s_lm (150 f) have disjoint lifetimes -> overlay.
    __shared__ __align__(16) float s_u[WPB][325];
    __shared__ unsigned char s_cls[WPB][32];   // slot*6 + pair
    __shared__ unsigned char s_pc[WPB][32];    // pair*5 + track
    __shared__ float    s_mics[12];
    __shared__ float    s_gl[WPB][6];          // per-group best cost
    __shared__ int      s_gc[WPB][6];          // per-group correct count
    __shared__ double   s_wl[WPB];
    __shared__ int      s_wc[WPB], s_wn[WPB];

    const int tid  = threadIdx.x;
    const int w    = tid >> 5;
    const int lane = tid & 31;
    const int bt   = blockIdx.x * WPB + w;

    float* s_tgt = s_u[w];   // phase 1
    float* s_lm  = s_u[w];   // phase 2 (pair*25 + slot*5 + track)

    // ---- stage inputs ----
    {
        const float2* pb2 = (const float2*)(pred + (size_t)bt * 390u); // even -> 8B aligned
        float2* sp2 = (float2*)&s_pred[w][0];
#pragma unroll
        for (int i = 0; i < 6; i++) sp2[lane + 32 * i] = pb2[lane + 32 * i];
        if (lane < 3) sp2[192 + lane] = pb2[192 + lane];
        const float* tb = target + (size_t)bt * 325u;
        for (int i = lane; i < 325; i += 32) s_tgt[i] = tb[i];
    }
    if (tid < 12) s_mics[tid] = mics[tid];
    __syncthreads();

    // ---- stable first-<=5 active selection via ballots (f = tr*13 + c) ----
    int f0 = lane, f1 = 32 + lane;
    int tr0 = f0 / 13, c0 = f0 - tr0 * 13;
    int tr1 = f1 / 13, c1 = f1 - tr1 * 13;
    unsigned b0 = __ballot_sync(0xffffffffu, s_tgt[tr0 * 65 + c0] != 0.0f);
    unsigned b1 = __ballot_sync(0xffffffffu, s_tgt[tr1 * 65 + c1] != 0.0f);
    int act64 = (s_tgt[4 * 65 + 12] != 0.0f) ? 1 : 0;   // f = 64
    unsigned long long bits = (unsigned long long)b0 |
                              ((unsigned long long)b1 << 32);
    int total = __popcll(bits) + act64;
    const int v = (total < 5) ? total : 5;

    // fsel on lanes 0..4 (others compute lane-0 copy), broadcast via shfl
    int fsel = 0;
    {
        int sl = (lane < 5) ? lane : 0;
        if (sl < v) {
            if (sl < __popcll(bits)) {
                unsigned long long t = bits;
#pragma unroll
                for (int j = 0; j < 4; j++)
                    if (j < sl) t &= t - 1;
                fsel = __ffsll((long long)t) - 1;
            } else {
                fsel = 64;
            }
        }
    }

    // ---- TDOA class per (slot, pair): 30 lanes ----
    {
        int s  = lane / 6;               // slot (lane<30)
        int pr = lane - s * 6;           // pair
        int f  = __shfl_sync(0xffffffffu, fsel, (s < 5) ? s : 0);
        if (lane < 30) {
            int cls = 0;
            if (s < v) {
                const int pa[6]  = {0, 0, 0, 1, 1, 2};
                const int pbx[6] = {1, 2, 3, 2, 3, 3};
                int tr = f / 13, c = f - tr * 13;
                float dist = s_tgt[tr * 65 + 52 + c];
                float sx = __fmul_rn(s_tgt[tr * 65 + 13 + c], dist);
                float sy = __fmul_rn(s_tgt[tr * 65 + 26 + c], dist);
                float sz = __fmul_rn(s_tgt[tr * 65 + 39 + c], dist);
                int ma = pa[pr], mb = pbx[pr];
                float dxa = __fsub_rn(sx, s_mics[ma * 3 + 0]);
                float dya = __fsub_rn(sy, s_mics[ma * 3 + 1]);
                float dza = __fsub_rn(sz, s_mics[ma * 3 + 2]);
                float dxb = __fsub_rn(sx, s_mics[mb * 3 + 0]);
                float dyb = __fsub_rn(sy, s_mics[mb * 3 + 1]);
                float dzb = __fsub_rn(sz, s_mics[mb * 3 + 2]);
                float qa = __fadd_rn(__fadd_rn(__fmul_rn(dxa, dxa), __fmul_rn(dya, dya)), __fmul_rn(dza, dza));
                float qb = __fadd_rn(__fadd_rn(__fmul_rn(dxb, dxb), __fmul_rn(dyb, dyb)), __fmul_rn(dzb, dzb));
                float tdoa = __fsub_rn(__fsqrt_rn(qa), __fsqrt_rn(qb));
                cls = (int)rintf(__fdiv_rn(__fmul_rn(tdoa, 24000.0f), 343.0f)) + 6;
            }
            s_cls[w][s * 6 + pr] = (unsigned char)cls;
        }
    }
    __syncwarp();

    // ---- log-softmax per (pair, track): 30 lanes, register-lean ----
    if (lane < 30) {
        const int pair  = lane / 5;
        const int track = lane - pair * 5;
        const float* xp = &s_pred[w][track * 6 + pair];   // stride 30

        float mx = -FLT_MAX;
        int   am = 0;
#pragma unroll
        for (int cl = 0; cl < 13; cl++) {
            float x = xp[cl * 30];
            if (x > mx) { mx = x; am = cl; }   // first-occurrence argmax
        }
        // XLA GPU 32-lane column-reduction tree (leaves 13..31 == 0)
        float t0 = __fadd_rn(__nv_expf(__fsub_rn(xp[0],      mx)), __nv_expf(__fsub_rn(xp[8 * 30],  mx)));
        float t1 = __fadd_rn(__nv_expf(__fsub_rn(xp[1 * 30], mx)), __nv_expf(__fsub_rn(xp[9 * 30],  mx)));
        float t2 = __fadd_rn(__nv_expf(__fsub_rn(xp[2 * 30], mx)), __nv_expf(__fsub_rn(xp[10 * 30], mx)));
        float t3 = __fadd_rn(__nv_expf(__fsub_rn(xp[3 * 30], mx)), __nv_expf(__fsub_rn(xp[11 * 30], mx)));
        float t4 = __fadd_rn(__nv_expf(__fsub_rn(xp[4 * 30], mx)), __nv_expf(__fsub_rn(xp[12 * 30], mx)));
        float u0 = __fadd_rn(t0, t4);
        float u1 = __fadd_rn(t1, __nv_expf(__fsub_rn(xp[5 * 30], mx)));
        float u2 = __fadd_rn(t2, __nv_expf(__fsub_rn(xp[6 * 30], mx)));
        float u3 = __fadd_rn(t3, __nv_expf(__fsub_rn(xp[7 * 30], mx)));
        float sm = __fadd_rn(__fadd_rn(u0, u2), __fadd_rn(u1, u3));
        float lse = __nv_logf(sm);
        s_pc[w][pair * 5 + track] = (unsigned char)am;
        float vals[5];
#pragma unroll
        for (int k = 0; k < 5; k++) {
            int idx = (k < v) ? (int)s_cls[w][k * 6 + pair] : 0;
            float xv = xp[idx * 30];
            vals[k] = (k < v) ? __fsub_rn(lse, __fsub_rn(xv, mx)) : 0.0f;
        }
        __syncwarp(0x3fffffffu);   // s_tgt fully dead before lm overwrite
#pragma unroll
        for (int k = 0; k < 5; k++)
            s_lm[pair * 25 + k * 5 + track] = vals[k];
    }
    __syncwarp();

    // ---- perm argmin: group g (5 lanes) owns pair g; lane lig = digit p0 ----
    // pe = p0*24 + i1*6 + i2*2 + c, enumerated strictly ascending per lane, so
    // the lazy-division rule (div only on strict raw improvement) reproduces
    // the reference first-occurrence argmin bitwise. Zero rows (slot k >= v)
    // make suffix-permuted costs bitwise equal (lm >= 0, no -0), so only block
    // starts are evaluated: v==3 -> cand1 only (even pe); v==2 -> i1 level;
    // v<=1 -> single candidate per lane.
    const int g   = (lane < 30) ? (lane / 5) : 6;
    const int lig = lane - g * 5;     // == p0 for g < 6
    const float* lm = &s_lm[g * 25];

    float bs0 = FLT_MAX, bcst = FLT_MAX;
    int   bidx = 1 << 20;

    if (g < 6) {
        const float a0 = lm[lig];               // row 0, track p0
        const int   pe0 = lig * 24;
        unsigned rem4 = nib_remove(0x43210u, lig);

#define LAZY_CAND(S0, PE)                                        \
        do {                                                     \
            float _s0 = (S0);                                    \
            if (_s0 < bs0) {                                     \
                float _c = __fdiv_rn(_s0, 5.0f);                 \
                if (_c < bcst) { bcst = _c; bidx = (PE); }       \
                bs0 = _s0;                                       \
            }                                                    \
        } while (0)

        if (v >= 3) {
            const bool both = (v >= 4);
#pragma unroll 1
            for (int i1 = 0; i1 < 4; i1++) {
                int p1 = (rem4 >> (4 * i1)) & 15;
                float a1 = lm[5 + p1];
                unsigned rem3 = nib_remove(rem4, i1);
#pragma unroll 1
                for (int i2 = 0; i2 < 3; i2++) {
                    int p2 = (rem3 >> (4 * i2)) & 15;
                    float a2 = lm[10 + p2];
                    unsigned rem2 = nib_remove(rem3, i2);
                    int p3a = rem2 & 15;
                    int p4a = (rem2 >> 4) & 15;
                    int pe = pe0 + i1 * 6 + i2 * 2;
                    // cand1: (p3,p4) = (p3a,p4a)  [lex first, p3a < p4a]
                    {
                        float a3 = lm[15 + p3a];
                        float a4 = lm[20 + p4a];
                        float s0 = __fadd_rn(__fadd_rn(__fadd_rn(a0, a4), a2),
                                             __fadd_rn(a1, a3));
                        LAZY_CAND(s0, pe);
                    }
                    if (both) {  // cand2: (p4a,p3a)
                        float a3 = lm[15 + p4a];
                        float a4 = lm[20 + p3a];
                        float s0 = __fadd_rn(__fadd_rn(__fadd_rn(a0, a4), a2),
                                             __fadd_rn(a1, a3));
                        LAZY_CAND(s0, pe + 1);
                    }
                }
            }
        } else if (v == 2) {
            // rows 2..4 zero: s0 = ((a0+0)+0)+(a1+0) == fadd(a0,a1) bitwise
#pragma unroll 1
            for (int i1 = 0; i1 < 4; i1++) {
                int p1 = (rem4 >> (4 * i1)) & 15;
                float s0 = __fadd_rn(a0, lm[5 + p1]);
                LAZY_CAND(s0, pe0 + i1 * 6);
            }
        } else {
            // v<=1: rows 1..4 zero: s0 == a0 (a0 == 0 too when v == 0)
            LAZY_CAND(a0, pe0);
        }
#undef LAZY_CAND
    }

    // group reduce over 5 lanes (offsets 4,2,1, guarded)
#pragma unroll
    for (int off = 4; off; off >>= 1) {
        float ov = __shfl_down_sync(0xffffffffu, bcst, off);
        int   oi = __shfl_down_sync(0xffffffffu, bidx, off);
        if (lig + off < 5 && g < 6) {
            if (ov < bcst || (ov == bcst && oi < bidx)) { bcst = ov; bidx = oi; }
        }
    }

    // group leaders: accuracy count + stash results
    if (g < 6 && lig == 0) {
        unsigned pk = perm_digits(bidx);
        int corr = 0;
#pragma unroll
        for (int i = 0; i < 5; i++) {
            int s = (pk >> (4 * i)) & 15;   // tgt_perm[i] = tgt[perm[i]]
            if (s < v && (int)s_pc[w][g * 5 + i] == (int)s_cls[w][s * 6 + g]) corr++;
        }
        s_gl[w][g] = bcst;
        s_gc[w][g] = corr;
    }
    __syncwarp();

    if (lane == 0) {
        double wl = 0.0;
        int    wc = 0;
#pragma unroll
        for (int gg = 0; gg < 6; gg++) {
            wl += (double)s_gl[w][gg];
            wc += s_gc[w][gg];
        }
        s_wl[w] = wl;
        s_wc[w] = wc;
        s_wn[w] = 6 * v;
    }
    __syncthreads();

    // ---- block accumulate -> buckets; last block finalizes output ----
    if (tid == 0) {
        double L = 0.0;
        int    C = 0, NP = 0;
#pragma unroll
        for (int i = 0; i < WPB; i++) { L += s_wl[i]; C += s_wc[i]; NP += s_wn[i]; }
        int bk = blockIdx.x & (NBUCK - 1);
        atomicAdd(&g_bl[bk], L);
        atomicAdd(&g_bc[bk], (unsigned long long)C);
        atomicAdd(&g_bn[bk], (unsigned long long)NP);
        __threadfence();
    }
    if (w == 0) {
        unsigned t = 0;
        if (lane == 0) t = atomicInc(&g_cnt, NBLK - 1);  // wraps -> clean state
        t = __shfl_sync(0xffffffffu, t, 0);
        if (t == NBLK - 1) {
            double             L = g_bl[lane];
            unsigned long long C = g_bc[lane];
            unsigned long long N = g_bn[lane];
            g_bl[lane] = 0.0;    // re-zero for next replay
            g_bc[lane] = 0ull;
            g_bn[lane] = 0ull;
#pragma unroll
            for (int off = 16; off; off >>= 1) {
                L += __shfl_down_sync(0xffffffffu, L, off);
                C += __shfl_down_sync(0xffffffffu, C, off);
                N += __shfl_down_sync(0xffffffffu, N, off);
            }
            if (lane == 0) {
                if (nout >= 1) out[0] = (float)(L / 192000.0);
                if (nout >= 2) out[1] = (N > 0) ? (float)((double)C / (double)N) : 0.0f;
            }
        }
    }
}

extern "C" void kernel_launch(void* const* d_in, const int* in_sizes, int n_in,
                              void* d_out, int out_size) {
    const float* pred   = (const float*)d_in[0];
    const float* target = (const float*)d_in[1];
    const float* mics   = (const float*)d_in[2];
    (void)in_sizes; (void)n_in;

    tdoa_main<<<NBLK, 256>>>(pred, target, mics, (float*)d_out, out_size);
}

// round 10
// speedup vs baseline: 1.1573x; 1.1573x over previous
#include <cuda_runtime.h>
#include <math.h>
#include <float.h>

// Accurate libdevice math (same routines XLA GPU lowers f32 exp/log to).
extern "C" __device__ float __nv_expf(float);
extern "C" __device__ float __nv_logf(float);

// B=64, T=500 -> 32000 (b,t) rows; NLOGIT=13, TR=5, P=6 pairs.
// pred  : (64,500,13,5,6) f32 -> 390 floats per (b,t)
// target: (64,500,5,5,13) f32 -> 325 floats per (b,t)
// mic_locs: (4,3) f32 ; out: [loss, acc] f32
//
// 256 threads = 8 warps, one (b,t) row per warp.
// Perm-argmin: 6 groups of 5 lanes; group g owns mic-pair g; lane lig owns
// the contiguous perm block pe in [24*lig, 24*lig+24) (first digit p0 = lig).

#define NBT    32000
#define WPB    8
#define NBLK   (NBT / WPB)   // 4000
#define NBUCK  32

__device__ double             g_bl[NBUCK];   // zero-init; last block re-zeroes
__device__ unsigned long long g_bc[NBUCK];
__device__ unsigned long long g_bn[NBUCK];
__device__ unsigned           g_cnt;         // wraps to 0 every full launch

// Lexicographic (itertools) permutation -> packed 5-bit fields (5k + digit_k).
__device__ __forceinline__ unsigned perm_pack5(int p) {
    int avail[5] = {0, 1, 2, 3, 4};
    const int fact[4] = {24, 6, 2, 1};
    unsigned ep = 0;
#pragma unroll
    for (int i = 0; i < 4; i++) {
        int d = p / fact[i];
        p -= d * fact[i];
        ep |= (unsigned)(5 * i + avail[d]) << (5 * i);
#pragma unroll
        for (int j = 0; j < 4; j++)
            if (j >= d) avail[j] = avail[j + 1];
    }
    ep |= (unsigned)(20 + avail[0]) << 20;
    return ep;
}

__global__ __launch_bounds__(256, 8) void tdoa_main(
    const float* __restrict__ pred,
    const float* __restrict__ target,
    const float* __restrict__ mics,
    float* __restrict__ out, int nout)
{
    __shared__ __align__(16) float s_pred[WPB][390];  // cl*30 + track*6 + pair
    // s_tgt (325 f) and s_lm (150 f) have disjoint lifetimes -> overlay.
    __shared__ __align__(16) float s_u[WPB][325];
    __shared__ unsigned char s_cls[WPB][32];   // slot*6 + pair
    __shared__ unsigned char s_pc[WPB][32];    // pair*5 + track
    __shared__ unsigned s_eperm[128];          // 5-bit (5k+digit); [120..]=0
    __shared__ float    s_mics[12];
    __shared__ float    s_gl[WPB][6];          // per-group best cost
    __shared__ int      s_gc[WPB][6];          // per-group correct count
    __shared__ double   s_wl[WPB];
    __shared__ int      s_wc[WPB], s_wn[WPB];

    const int tid  = threadIdx.x;
    const int w    = tid >> 5;
    const int lane = tid & 31;
    const int bt   = blockIdx.x * WPB + w;

    float* s_tgt = s_u[w];   // phase 1
    float* s_lm  = s_u[w];   // phase 2 (pair*25 + slot*5 + track)

    // ---- stage inputs + block tables ----
    {
        const float2* pb2 = (const float2*)(pred + (size_t)bt * 390u); // even -> 8B aligned
        float2* sp2 = (float2*)&s_pred[w][0];
#pragma unroll
        for (int i = 0; i < 6; i++) sp2[lane + 32 * i] = pb2[lane + 32 * i];
        if (lane < 3) sp2[192 + lane] = pb2[192 + lane];
        const float* tb = target + (size_t)bt * 325u;
        for (int i = lane; i < 325; i += 32) s_tgt[i] = tb[i];
    }
    if (tid < 128) s_eperm[tid] = (tid < 120) ? perm_pack5(tid) : 0u;
    if (tid < 12)  s_mics[tid] = mics[tid];
    __syncthreads();

    // ---- stable first-<=5 active selection via ballots (f = tr*13 + c) ----
    int f0 = lane, f1 = 32 + lane;
    int tr0 = f0 / 13, c0 = f0 - tr0 * 13;
    int tr1 = f1 / 13, c1 = f1 - tr1 * 13;
    unsigned b0 = __ballot_sync(0xffffffffu, s_tgt[tr0 * 65 + c0] != 0.0f);
    unsigned b1 = __ballot_sync(0xffffffffu, s_tgt[tr1 * 65 + c1] != 0.0f);
    int act64 = (s_tgt[4 * 65 + 12] != 0.0f) ? 1 : 0;   // f = 64
    unsigned long long bits = (unsigned long long)b0 |
                              ((unsigned long long)b1 << 32);
    int total = __popcll(bits) + act64;
    const int v = (total < 5) ? total : 5;

    // fsel on lanes 0..4 (others compute lane-0 copy), broadcast via shfl
    int fsel = 0;
    {
        int sl = (lane < 5) ? lane : 0;
        if (sl < v) {
            if (sl < __popcll(bits)) {
                unsigned long long t = bits;
#pragma unroll
                for (int j = 0; j < 4; j++)
                    if (j < sl) t &= t - 1;
                fsel = __ffsll((long long)t) - 1;
            } else {
                fsel = 64;
            }
        }
    }

    // ---- TDOA class per (slot, pair): 30 lanes ----
    {
        int s  = lane / 6;               // slot (lane<30)
        int pr = lane - s * 6;           // pair
        int f  = __shfl_sync(0xffffffffu, fsel, (s < 5) ? s : 0);
        if (lane < 30) {
            int cls = 0;
            if (s < v) {
                const int pa[6]  = {0, 0, 0, 1, 1, 2};
                const int pbx[6] = {1, 2, 3, 2, 3, 3};
                int tr = f / 13, c = f - tr * 13;
                float dist = s_tgt[tr * 65 + 52 + c];
                float sx = __fmul_rn(s_tgt[tr * 65 + 13 + c], dist);
                float sy = __fmul_rn(s_tgt[tr * 65 + 26 + c], dist);
                float sz = __fmul_rn(s_tgt[tr * 65 + 39 + c], dist);
                int ma = pa[pr], mb = pbx[pr];
                float dxa = __fsub_rn(sx, s_mics[ma * 3 + 0]);
                float dya = __fsub_rn(sy, s_mics[ma * 3 + 1]);
                float dza = __fsub_rn(sz, s_mics[ma * 3 + 2]);
                float dxb = __fsub_rn(sx, s_mics[mb * 3 + 0]);
                float dyb = __fsub_rn(sy, s_mics[mb * 3 + 1]);
                float dzb = __fsub_rn(sz, s_mics[mb * 3 + 2]);
                float qa = __fadd_rn(__fadd_rn(__fmul_rn(dxa, dxa), __fmul_rn(dya, dya)), __fmul_rn(dza, dza));
                float qb = __fadd_rn(__fadd_rn(__fmul_rn(dxb, dxb), __fmul_rn(dyb, dyb)), __fmul_rn(dzb, dzb));
                float tdoa = __fsub_rn(__fsqrt_rn(qa), __fsqrt_rn(qb));
                cls = (int)rintf(__fdiv_rn(__fmul_rn(tdoa, 24000.0f), 343.0f)) + 6;
            }
            s_cls[w][s * 6 + pr] = (unsigned char)cls;
        }
    }
    __syncwarp();

    // ---- log-softmax per (pair, track): 30 lanes, register-lean ----
    if (lane < 30) {
        const int pair  = lane / 5;
        const int track = lane - pair * 5;
        const float* xp = &s_pred[w][track * 6 + pair];   // stride 30

        float mx = -FLT_MAX;
        int   am = 0;
#pragma unroll
        for (int cl = 0; cl < 13; cl++) {
            float x = xp[cl * 30];
            if (x > mx) { mx = x; am = cl; }   // first-occurrence argmax
        }
        // XLA GPU 32-lane column-reduction tree (leaves 13..31 == 0)
        float t0 = __fadd_rn(__nv_expf(__fsub_rn(xp[0],      mx)), __nv_expf(__fsub_rn(xp[8 * 30],  mx)));
        float t1 = __fadd_rn(__nv_expf(__fsub_rn(xp[1 * 30], mx)), __nv_expf(__fsub_rn(xp[9 * 30],  mx)));
        float t2 = __fadd_rn(__nv_expf(__fsub_rn(xp[2 * 30], mx)), __nv_expf(__fsub_rn(xp[10 * 30], mx)));
        float t3 = __fadd_rn(__nv_expf(__fsub_rn(xp[3 * 30], mx)), __nv_expf(__fsub_rn(xp[11 * 30], mx)));
        float t4 = __fadd_rn(__nv_expf(__fsub_rn(xp[4 * 30], mx)), __nv_expf(__fsub_rn(xp[12 * 30], mx)));
        float u0 = __fadd_rn(t0, t4);
        float u1 = __fadd_rn(t1, __nv_expf(__fsub_rn(xp[5 * 30], mx)));
        float u2 = __fadd_rn(t2, __nv_expf(__fsub_rn(xp[6 * 30], mx)));
        float u3 = __fadd_rn(t3, __nv_expf(__fsub_rn(xp[7 * 30], mx)));
        float sm = __fadd_rn(__fadd_rn(u0, u2), __fadd_rn(u1, u3));
        float lse = __nv_logf(sm);
        s_pc[w][pair * 5 + track] = (unsigned char)am;
        float vals[5];
#pragma unroll
        for (int k = 0; k < 5; k++) {
            int idx = (k < v) ? (int)s_cls[w][k * 6 + pair] : 0;
            float xv = xp[idx * 30];
            vals[k] = (k < v) ? __fsub_rn(lse, __fsub_rn(xv, mx)) : 0.0f;
        }
        __syncwarp(0x3fffffffu);   // s_tgt fully dead before lm overwrite
#pragma unroll
        for (int k = 0; k < 5; k++)
            s_lm[pair * 25 + k * 5 + track] = vals[k];
    }
    __syncwarp();

    // ---- perm argmin: group g (5 lanes) owns pair g; lane lig owns the
    // contiguous block pe in [24*lig, 24*lig+24), so digit p0 == lig and
    // a0 = lm[lig] is loop-invariant. Zero rows (slot k >= v) make all perms
    // sharing a v-prefix bitwise-equal (lm >= 0), so only block starts
    // pe = pe0 + j*fac are evaluated: cnt[v] = {1,1,4,12,24,24} per lane.
    // Two contiguous ascending chains + lazy division (div only on strict raw
    // improvement) reproduce the reference first-occurrence argmin bitwise.
    const int g   = (lane < 30) ? (lane / 5) : 6;
    const int lig = lane - g * 5;     // == p0 for g < 6
    const float* lm = &s_lm[g * 25];

    static __device__ const int FACV[6] = {24, 24, 6, 2, 1, 1};
    static __device__ const int CNTV[6] = {1, 1, 4, 12, 24, 24};
    const int fac = FACV[v];
    const int cnt = (g < 6) ? CNTV[v] : 0;
    const int pe0 = lig * 24;
    const float a0 = (g < 6) ? lm[lig] : 0.0f;
    const int half = (cnt + 1) >> 1;

    float bs0A = FLT_MAX, bcA = FLT_MAX;  int biA = 1 << 20;
    float bs0B = FLT_MAX, bcB = FLT_MAX;  int biB = 1 << 20;
#pragma unroll 1
    for (int jj = 0; jj < half; jj++) {
        {   // chain A: j = jj  (pe ascending)
            int pe = pe0 + jj * fac;
            unsigned ep = s_eperm[pe];
            float a1 = lm[(ep >> 5)  & 31];
            float a2 = lm[(ep >> 10) & 31];
            float a3 = lm[(ep >> 15) & 31];
            float a4 = lm[(ep >> 20) & 31];
            float s0 = __fadd_rn(__fadd_rn(__fadd_rn(a0, a4), a2),
                                 __fadd_rn(a1, a3));
            if (s0 < bs0A) {
                float cst = __fdiv_rn(s0, 5.0f);
                if (cst < bcA) { bcA = cst; biA = pe; }
                bs0A = s0;
            }
        }
        int j2 = jj + half;
        if (j2 < cnt) {   // chain B: j = jj + half (pe ascending)
            int pe = pe0 + j2 * fac;
            unsigned ep = s_eperm[pe];
            float a1 = lm[(ep >> 5)  & 31];
            float a2 = lm[(ep >> 10) & 31];
            float a3 = lm[(ep >> 15) & 31];
            float a4 = lm[(ep >> 20) & 31];
            float s0 = __fadd_rn(__fadd_rn(__fadd_rn(a0, a4), a2),
                                 __fadd_rn(a1, a3));
            if (s0 < bs0B) {
                float cst = __fdiv_rn(s0, 5.0f);
                if (cst < bcB) { bcB = cst; biB = pe; }
                bs0B = s0;
            }
        }
    }
    float bcst = bcA; int bidx = biA;
    if (bcB < bcst || (bcB == bcst && biB < bidx)) { bcst = bcB; bidx = biB; }

    // group reduce over 5 lanes (offsets 4,2,1, guarded)
#pragma unroll
    for (int off = 4; off; off >>= 1) {
        float ov = __shfl_down_sync(0xffffffffu, bcst, off);
        int   oi = __shfl_down_sync(0xffffffffu, bidx, off);
        if (lig + off < 5 && g < 6) {
            if (ov < bcst || (ov == bcst && oi < bidx)) { bcst = ov; bidx = oi; }
        }
    }

    // group leaders: accuracy count + stash results
    if (g < 6 && lig == 0) {
        unsigned ep = s_eperm[bidx];
        int corr = 0;
#pragma unroll
        for (int i = 0; i < 5; i++) {
            int s = (int)((ep >> (5 * i)) & 31) - 5 * i;  // tgt_perm[i]
            if (s < v && (int)s_pc[w][g * 5 + i] == (int)s_cls[w][s * 6 + g]) corr++;
        }
        s_gl[w][g] = bcst;
        s_gc[w][g] = corr;
    }
    __syncwarp();

    if (lane == 0) {
        double wl = 0.0;
        int    wc = 0;
#pragma unroll
        for (int gg = 0; gg < 6; gg++) {
            wl += (double)s_gl[w][gg];
            wc += s_gc[w][gg];
        }
        s_wl[w] = wl;
        s_wc[w] = wc;
        s_wn[w] = 6 * v;
    }
    __syncthreads();

    // ---- block accumulate -> buckets; last block finalizes output ----
    if (tid == 0) {
        double L = 0.0;
        int    C = 0, NP = 0;
#pragma unroll
        for (int i = 0; i < WPB; i++) { L += s_wl[i]; C += s_wc[i]; NP += s_wn[i]; }
        int bk = blockIdx.x & (NBUCK - 1);
        atomicAdd(&g_bl[bk], L);
        atomicAdd(&g_bc[bk], (unsigned long long)C);
        atomicAdd(&g_bn[bk], (unsigned long long)NP);
        __threadfence();
    }
    if (w == 0) {
        unsigned t = 0;
        if (lane == 0) t = atomicInc(&g_cnt, NBLK - 1);  // wraps -> clean state
        t = __shfl_sync(0xffffffffu, t, 0);
        if (t == NBLK - 1) {
            double             L = g_bl[lane];
            unsigned long long C = g_bc[lane];
            unsigned long long N = g_bn[lane];
            g_bl[lane] = 0.0;    // re-zero for next replay
            g_bc[lane] = 0ull;
            g_bn[lane] = 0ull;
#pragma unroll
            for (int off = 16; off; off >>= 1) {
                L += __shfl_down_sync(0xffffffffu, L, off);
                C += __shfl_down_sync(0xffffffffu, C, off);
                N += __shfl_down_sync(0xffffffffu, N, off);
            }
            if (lane == 0) {
                if (nout >= 1) out[0] = (float)(L / 192000.0);
                if (nout >= 2) out[1] = (N > 0) ? (float)((double)C / (double)N) : 0.0f;
            }
        }
    }
}

extern "C" void kernel_launch(void* const* d_in, const int* in_sizes, int n_in,
                              void* d_out, int out_size) {
    const float* pred   = (const float*)d_in[0];
    const float* target = (const float*)d_in[1];
    const float* mics   = (const float*)d_in[2];
    (void)in_sizes; (void)n_in;

    tdoa_main<<<NBLK, 256>>>(pred, target, mics, (float*)d_out, out_size);
}

// round 11
// speedup vs baseline: 1.2665x; 1.0943x over previous
#include <cuda_runtime.h>
#include <math.h>
#include <float.h>

// Accurate libdevice math (same routines XLA GPU lowers f32 exp/log to).
extern "C" __device__ float __nv_expf(float);
extern "C" __device__ float __nv_logf(float);

// B=64, T=500 -> 32000 (b,t) rows; NLOGIT=13, TR=5, P=6 pairs.
// pred  : (64,500,13,5,6) f32 -> 390 floats per (b,t)
// target: (64,500,5,5,13) f32 -> 325 floats per (b,t)
// mic_locs: (4,3) f32 ; out: [loss, acc] f32
//
// 256 threads = 8 warps, one (b,t) row per warp.
// Perm-argmin: 6 groups of 5 lanes; group g owns mic-pair g; lane lig owns
// the contiguous perm block pe in [24*lig, 24*lig+24) (first digit p0 = lig).
// Cost tree ((a0+a4)+a2)+(a1+a3): the (a1+a3) term is precomputed per pair
// into T13[25] (bitwise the same fadd), so each eval is 3 LDS + 3 FADD.

#define NBT    32000
#define WPB    8
#define NBLK   (NBT / WPB)   // 4000
#define NBUCK  32

__device__ double             g_bl[NBUCK];   // zero-init; last block re-zeroes
__device__ unsigned long long g_bc[NBUCK];
__device__ unsigned long long g_bn[NBUCK];
__device__ unsigned           g_cnt;         // wraps to 0 every full launch

// Lexicographic (itertools) perm index -> digits d[0..4].
__device__ __forceinline__ void perm_digits(int p, int* d) {
    int avail[5] = {0, 1, 2, 3, 4};
    const int fact[4] = {24, 6, 2, 1};
#pragma unroll
    for (int i = 0; i < 4; i++) {
        int q = p / fact[i];
        p -= q * fact[i];
        d[i] = avail[q];
#pragma unroll
        for (int j = 0; j < 4; j++)
            if (j >= q) avail[j] = avail[j + 1];
    }
    d[4] = avail[0];
}

__global__ __launch_bounds__(256, 8) void tdoa_main(
    const float* __restrict__ pred,
    const float* __restrict__ target,
    const float* __restrict__ mics,
    float* __restrict__ out, int nout)
{
    __shared__ __align__(16) float s_pred[WPB][390];  // cl*30 + track*6 + pair
    // Overlay: phase 1 = s_tgt (325 f); phase 2 = s_lm (150 f) + T13 (150 f).
    __shared__ __align__(16) float s_u[WPB][325];
    __shared__ unsigned char s_cls[WPB][32];   // slot*6 + pair
    __shared__ unsigned char s_pc[WPB][32];    // pair*5 + track
    // Packed byte-offsets per perm: b0=4*(p1*5+p3), b1=4*(10+p2), b2=4*(20+p4)
    __shared__ unsigned s_ep2[128];            // [120..127] = 0
    __shared__ float    s_mics[12];
    __shared__ float    s_gl[WPB][6];          // per-group best cost
    __shared__ int      s_gc[WPB][6];          // per-group correct count
    __shared__ double   s_wl[WPB];
    __shared__ int      s_wc[WPB], s_wn[WPB];

    const int tid  = threadIdx.x;
    const int w    = tid >> 5;
    const int lane = tid & 31;
    const int bt   = blockIdx.x * WPB + w;

    float* s_tgt = s_u[w];           // phase 1
    float* s_lm  = s_u[w];           // phase 2: [0..149]  pair*25 + slot*5 + track
    float* s_t13 = s_u[w] + 150;     // phase 2: [150..299] pair*25 + p1*5 + p3

    // ---- stage inputs + block tables ----
    {
        const float2* pb2 = (const float2*)(pred + (size_t)bt * 390u); // even -> 8B aligned
        float2* sp2 = (float2*)&s_pred[w][0];
#pragma unroll
        for (int i = 0; i < 6; i++) sp2[lane + 32 * i] = pb2[lane + 32 * i];
        if (lane < 3) sp2[192 + lane] = pb2[192 + lane];
        const float* tb = target + (size_t)bt * 325u;
        for (int i = lane; i < 325; i += 32) s_tgt[i] = tb[i];
    }
    if (tid < 128) {
        unsigned ep = 0;
        if (tid < 120) {
            int d[5];
            perm_digits(tid, d);
            ep  = (unsigned)(4 * (d[1] * 5 + d[3]));
            ep |= (unsigned)(4 * (10 + d[2])) << 8;
            ep |= (unsigned)(4 * (20 + d[4])) << 16;
        }
        s_ep2[tid] = ep;
    }
    if (tid < 12) s_mics[tid] = mics[tid];
    __syncthreads();

    // ---- stable first-<=5 active selection via ballots (f = tr*13 + c) ----
    int f0 = lane, f1 = 32 + lane;
    int tr0 = f0 / 13, c0 = f0 - tr0 * 13;
    int tr1 = f1 / 13, c1 = f1 - tr1 * 13;
    unsigned b0 = __ballot_sync(0xffffffffu, s_tgt[tr0 * 65 + c0] != 0.0f);
    unsigned b1 = __ballot_sync(0xffffffffu, s_tgt[tr1 * 65 + c1] != 0.0f);
    int act64 = (s_tgt[4 * 65 + 12] != 0.0f) ? 1 : 0;   // f = 64
    unsigned long long bits = (unsigned long long)b0 |
                              ((unsigned long long)b1 << 32);
    int total = __popcll(bits) + act64;
    const int v = (total < 5) ? total : 5;

    // fsel on lanes 0..4 (others compute lane-0 copy), broadcast via shfl
    int fsel = 0;
    {
        int sl = (lane < 5) ? lane : 0;
        if (sl < v) {
            if (sl < __popcll(bits)) {
                unsigned long long t = bits;
#pragma unroll
                for (int j = 0; j < 4; j++)
                    if (j < sl) t &= t - 1;
                fsel = __ffsll((long long)t) - 1;
            } else {
                fsel = 64;
            }
        }
    }

    // ---- TDOA class per (slot, pair): 30 lanes ----
    {
        int s  = lane / 6;               // slot (lane<30)
        int pr = lane - s * 6;           // pair
        int f  = __shfl_sync(0xffffffffu, fsel, (s < 5) ? s : 0);
        if (lane < 30) {
            int cls = 0;
            if (s < v) {
                const int pa[6]  = {0, 0, 0, 1, 1, 2};
                const int pbx[6] = {1, 2, 3, 2, 3, 3};
                int tr = f / 13, c = f - tr * 13;
                float dist = s_tgt[tr * 65 + 52 + c];
                float sx = __fmul_rn(s_tgt[tr * 65 + 13 + c], dist);
                float sy = __fmul_rn(s_tgt[tr * 65 + 26 + c], dist);
                float sz = __fmul_rn(s_tgt[tr * 65 + 39 + c], dist);
                int ma = pa[pr], mb = pbx[pr];
                float dxa = __fsub_rn(sx, s_mics[ma * 3 + 0]);
                float dya = __fsub_rn(sy, s_mics[ma * 3 + 1]);
                float dza = __fsub_rn(sz, s_mics[ma * 3 + 2]);
                float dxb = __fsub_rn(sx, s_mics[mb * 3 + 0]);
                float dyb = __fsub_rn(sy, s_mics[mb * 3 + 1]);
                float dzb = __fsub_rn(sz, s_mics[mb * 3 + 2]);
                float qa = __fadd_rn(__fadd_rn(__fmul_rn(dxa, dxa), __fmul_rn(dya, dya)), __fmul_rn(dza, dza));
                float qb = __fadd_rn(__fadd_rn(__fmul_rn(dxb, dxb), __fmul_rn(dyb, dyb)), __fmul_rn(dzb, dzb));
                float tdoa = __fsub_rn(__fsqrt_rn(qa), __fsqrt_rn(qb));
                cls = (int)rintf(__fdiv_rn(__fmul_rn(tdoa, 24000.0f), 343.0f)) + 6;
            }
            s_cls[w][s * 6 + pr] = (unsigned char)cls;
        }
    }
    __syncwarp();

    // ---- log-softmax per (pair, track): 30 lanes, register-lean ----
    if (lane < 30) {
        const int pair  = lane / 5;
        const int track = lane - pair * 5;
        const float* xp = &s_pred[w][track * 6 + pair];   // stride 30

        float mx = -FLT_MAX;
        int   am = 0;
#pragma unroll
        for (int cl = 0; cl < 13; cl++) {
            float x = xp[cl * 30];
            if (x > mx) { mx = x; am = cl; }   // first-occurrence argmax
        }
        // XLA GPU 32-lane column-reduction tree (leaves 13..31 == 0)
        float t0 = __fadd_rn(__nv_expf(__fsub_rn(xp[0],      mx)), __nv_expf(__fsub_rn(xp[8 * 30],  mx)));
        float t1 = __fadd_rn(__nv_expf(__fsub_rn(xp[1 * 30], mx)), __nv_expf(__fsub_rn(xp[9 * 30],  mx)));
        float t2 = __fadd_rn(__nv_expf(__fsub_rn(xp[2 * 30], mx)), __nv_expf(__fsub_rn(xp[10 * 30], mx)));
        float t3 = __fadd_rn(__nv_expf(__fsub_rn(xp[3 * 30], mx)), __nv_expf(__fsub_rn(xp[11 * 30], mx)));
        float t4 = __fadd_rn(__nv_expf(__fsub_rn(xp[4 * 30], mx)), __nv_expf(__fsub_rn(xp[12 * 30], mx)));
        float u0 = __fadd_rn(t0, t4);
        float u1 = __fadd_rn(t1, __nv_expf(__fsub_rn(xp[5 * 30], mx)));
        float u2 = __fadd_rn(t2, __nv_expf(__fsub_rn(xp[6 * 30], mx)));
        float u3 = __fadd_rn(t3, __nv_expf(__fsub_rn(xp[7 * 30], mx)));
        float sm = __fadd_rn(__fadd_rn(u0, u2), __fadd_rn(u1, u3));
        float lse = __nv_logf(sm);
        s_pc[w][pair * 5 + track] = (unsigned char)am;
        float vals[5];
#pragma unroll
        for (int k = 0; k < 5; k++) {
            int idx = (k < v) ? (int)s_cls[w][k * 6 + pair] : 0;
            float xv = xp[idx * 30];
            vals[k] = (k < v) ? __fsub_rn(lse, __fsub_rn(xv, mx)) : 0.0f;
        }
        __syncwarp(0x3fffffffu);   // s_tgt fully dead before lm overwrite
#pragma unroll
        for (int k = 0; k < 5; k++)
            s_lm[pair * 25 + k * 5 + track] = vals[k];
    }
    __syncwarp();

    // ---- build T13[pair][p1][p3] = fadd(lm1[p1], lm3[p3]) (exact tree op) ----
#pragma unroll
    for (int e = lane; e < 150; e += 32) {
        int pr = e / 25, r = e - pr * 25;
        int i = r / 5, j = r - i * 5;
        s_t13[e] = __fadd_rn(s_lm[pr * 25 + 5 + i], s_lm[pr * 25 + 15 + j]);
    }
    __syncwarp();

    // ---- perm argmin: group g (5 lanes) owns pair g; lane lig owns the
    // contiguous block pe in [24*lig, 24*lig+24); a0 = lm[lig] loop-invariant.
    // Zero rows (slot k >= v) make perms sharing a v-prefix bitwise-equal
    // (lm > 0 valid, +0 pads), so only block starts pe = pe0 + j*fac are
    // evaluated: cnt = {1,1,4,12,24,24}[v]. Two ascending chains + lazy
    // division reproduce reference first-occurrence argmin bitwise.
    const int g   = (lane < 30) ? (lane / 5) : 6;
    const int lig = lane - g * 5;     // == p0 for g < 6
    const char* lmB  = (const char*)(s_lm  + g * 25);
    const char* t13B = (const char*)(s_t13 + g * 25);

    const int fac = (v >= 4) ? 1 : ((v == 3) ? 2 : ((v == 2) ? 6 : 24));
    const int cnt = (g >= 6) ? 0 : ((v >= 4) ? 24 : ((v == 3) ? 12 : ((v == 2) ? 4 : 1)));
    const int pe0 = lig * 24;
    const float a0 = (g < 6) ? ((const float*)lmB)[lig] : 0.0f;
    const int half = (cnt + 1) >> 1;

    float bs0A = FLT_MAX, bcA = FLT_MAX;  int biA = 1 << 20;
    float bs0B = FLT_MAX, bcB = FLT_MAX;  int biB = 1 << 20;
    int peA = pe0;
    int peB = pe0 + half * fac;
#pragma unroll 1
    for (int jj = 0; jj < half; jj++) {
        {   // chain A (pe ascending)
            unsigned ep = s_ep2[peA];
            float y  = *(const float*)(t13B + (ep & 255u));          // a1+a3
            float a2 = *(const float*)(lmB + ((ep >> 8) & 255u));
            float a4 = *(const float*)(lmB + (ep >> 16));
            float s0 = __fadd_rn(__fadd_rn(__fadd_rn(a0, a4), a2), y);
            if (s0 < bs0A) {
                float cst = __fdiv_rn(s0, 5.0f);
                if (cst < bcA) { bcA = cst; biA = peA; }
                bs0A = s0;
            }
        }
        if (jj + half < cnt) {   // chain B (pe ascending)
            unsigned ep = s_ep2[peB];
            float y  = *(const float*)(t13B + (ep & 255u));
            float a2 = *(const float*)(lmB + ((ep >> 8) & 255u));
            float a4 = *(const float*)(lmB + (ep >> 16));
            float s0 = __fadd_rn(__fadd_rn(__fadd_rn(a0, a4), a2), y);
            if (s0 < bs0B) {
                float cst = __fdiv_rn(s0, 5.0f);
                if (cst < bcB) { bcB = cst; biB = peB; }
                bs0B = s0;
            }
        }
        peA += fac;
        peB += fac;
    }
    float bcst = bcA; int bidx = biA;
    if (bcB < bcst || (bcB == bcst && biB < bidx)) { bcst = bcB; bidx = biB; }

    // group reduce over 5 lanes (offsets 4,2,1, guarded)
#pragma unroll
    for (int off = 4; off; off >>= 1) {
        float ov = __shfl_down_sync(0xffffffffu, bcst, off);
        int   oi = __shfl_down_sync(0xffffffffu, bidx, off);
        if (lig + off < 5 && g < 6) {
            if (ov < bcst || (ov == bcst && oi < bidx)) { bcst = ov; bidx = oi; }
        }
    }

    // group leaders: accuracy count + stash results
    if (g < 6 && lig == 0) {
        int d[5];
        perm_digits(bidx, d);
        int corr = 0;
#pragma unroll
        for (int i = 0; i < 5; i++) {
            int s = d[i];   // tgt_perm[i] = tgt[perm[i]]
            if (s < v && (int)s_pc[w][g * 5 + i] == (int)s_cls[w][s * 6 + g]) corr++;
        }
        s_gl[w][g] = bcst;
        s_gc[w][g] = corr;
    }
    __syncwarp();

    if (lane == 0) {
        double wl = 0.0;
        int    wc = 0;
#pragma unroll
        for (int gg = 0; gg < 6; gg++) {
            wl += (double)s_gl[w][gg];
            wc += s_gc[w][gg];
        }
        s_wl[w] = wl;
        s_wc[w] = wc;
        s_wn[w] = 6 * v;
    }
    __syncthreads();

    // ---- block accumulate -> buckets; last block finalizes output ----
    if (tid == 0) {
        double L = 0.0;
        int    C = 0, NP = 0;
#pragma unroll
        for (int i = 0; i < WPB; i++) { L += s_wl[i]; C += s_wc[i]; NP += s_wn[i]; }
        int bk = blockIdx.x & (NBUCK - 1);
        atomicAdd(&g_bl[bk], L);
        atomicAdd(&g_bc[bk], (unsigned long long)C);
        atomicAdd(&g_bn[bk], (unsigned long long)NP);
        __threadfence();
    }
    if (w == 0) {
        unsigned t = 0;
        if (lane == 0) t = atomicInc(&g_cnt, NBLK - 1);  // wraps -> clean state
        t = __shfl_sync(0xffffffffu, t, 0);
        if (t == NBLK - 1) {
            double             L = g_bl[lane];
            unsigned long long C = g_bc[lane];
            unsigned long long N = g_bn[lane];
            g_bl[lane] = 0.0;    // re-zero for next replay
            g_bc[lane] = 0ull;
            g_bn[lane] = 0ull;
#pragma unroll
            for (int off = 16; off; off >>= 1) {
                L += __shfl_down_sync(0xffffffffu, L, off);
                C += __shfl_down_sync(0xffffffffu, C, off);
                N += __shfl_down_sync(0xffffffffu, N, off);
            }
            if (lane == 0) {
                if (nout >= 1) out[0] = (float)(L / 192000.0);
                if (nout >= 2) out[1] = (N > 0) ? (float)((double)C / (double)N) : 0.0f;
            }
        }
    }
}

extern "C" void kernel_launch(void* const* d_in, const int* in_sizes, int n_in,
                              void* d_out, int out_size) {
    const float* pred   = (const float*)d_in[0];
    const float* target = (const float*)d_in[1];
    const float* mics   = (const float*)d_in[2];
    (void)in_sizes; (void)n_in;

    tdoa_main<<<NBLK, 256>>>(pred, target, mics, (float*)d_out, out_size);
}

// round 12
// speedup vs baseline: 1.2677x; 1.0009x over previous
#include <cuda_runtime.h>
#include <math.h>
#include <float.h>

// Accurate libdevice math (same routines XLA GPU lowers f32 exp/log to).
extern "C" __device__ float __nv_expf(float);
extern "C" __device__ float __nv_logf(float);

// B=64, T=500 -> 32000 (b,t) rows; NLOGIT=13, TR=5, P=6 pairs.
// pred  : (64,500,13,5,6) f32 -> 390 floats per (b,t)
// target: (64,500,5,5,13) f32 -> 325 floats per (b,t)
// mic_locs: (4,3) f32 ; out: [loss, acc] f32
//
// 256 threads = 8 warps, one (b,t) row per warp.
// Perm-argmin: 6 groups of 5 lanes; group g owns mic-pair g; lane lig owns
// the contiguous perm block pe in [24*lig, 24*lig+24) (first digit p0 = lig).
// Cost tree ((a0+a4)+a2)+(a1+a3): the (a1+a3) term is precomputed per pair
// into T13[25] (bitwise the same fadd), so each eval is 3 LDS + 3 FADD.

#define NBT    32000
#define WPB    8
#define NBLK   (NBT / WPB)   // 4000
#define NBUCK  32

__device__ double             g_bl[NBUCK];   // zero-init; last block re-zeroes
__device__ unsigned long long g_bc[NBUCK];
__device__ unsigned long long g_bn[NBUCK];
__device__ unsigned           g_cnt;         // wraps to 0 every full launch

// Lexicographic (itertools) perm index -> digits d[0..4].
__device__ __forceinline__ void perm_digits(int p, int* d) {
    int avail[5] = {0, 1, 2, 3, 4};
    const int fact[4] = {24, 6, 2, 1};
#pragma unroll
    for (int i = 0; i < 4; i++) {
        int q = p / fact[i];
        p -= q * fact[i];
        d[i] = avail[q];
#pragma unroll
        for (int j = 0; j < 4; j++)
            if (j >= q) avail[j] = avail[j + 1];
    }
    d[4] = avail[0];
}

__global__ __launch_bounds__(256, 8) void tdoa_main(
    const float* __restrict__ pred,
    const float* __restrict__ target,
    const float* __restrict__ mics,
    float* __restrict__ out, int nout)
{
    __shared__ __align__(16) float s_pred[WPB][390];  // cl*30 + track*6 + pair
    // Overlay: phase 1 = s_tgt (325 f); phase 2 = s_lm (150 f) + T13 (150 f).
    __shared__ __align__(16) float s_u[WPB][325];
    __shared__ unsigned char s_cls[WPB][32];   // slot*6 + pair
    __shared__ unsigned char s_pc[WPB][32];    // pair*5 + track
    // Packed byte-offsets per perm: b0=4*(p1*5+p3), b1=4*(10+p2), b2=4*(20+p4)
    __shared__ unsigned s_ep2[128];            // [120..127] = 0
    __shared__ float    s_mics[12];
    __shared__ float    s_gl[WPB][6];          // per-group best cost
    __shared__ int      s_gc[WPB][6];          // per-group correct count
    __shared__ double   s_wl[WPB];
    __shared__ int      s_wc[WPB], s_wn[WPB];

    const int tid  = threadIdx.x;
    const int w    = tid >> 5;
    const int lane = tid & 31;
    const int bt   = blockIdx.x * WPB + w;

    float* s_tgt = s_u[w];           // phase 1
    float* s_lm  = s_u[w];           // phase 2: [0..149]  pair*25 + slot*5 + track
    float* s_t13 = s_u[w] + 150;     // phase 2: [150..299] pair*25 + p1*5 + p3

    // ---- stage inputs + block tables ----
    {
        const float2* pb2 = (const float2*)(pred + (size_t)bt * 390u); // even -> 8B aligned
        float2* sp2 = (float2*)&s_pred[w][0];
#pragma unroll
        for (int i = 0; i < 6; i++) sp2[lane + 32 * i] = pb2[lane + 32 * i];
        if (lane < 3) sp2[192 + lane] = pb2[192 + lane];
        const float* tb = target + (size_t)bt * 325u;
        for (int i = lane; i < 325; i += 32) s_tgt[i] = tb[i];
    }
    if (tid < 128) {
        unsigned ep = 0;
        if (tid < 120) {
            int d[5];
            perm_digits(tid, d);
            ep  = (unsigned)(4 * (d[1] * 5 + d[3]));
            ep |= (unsigned)(4 * (10 + d[2])) << 8;
            ep |= (unsigned)(4 * (20 + d[4])) << 16;
        }
        s_ep2[tid] = ep;
    }
    if (tid < 12) s_mics[tid] = mics[tid];
    __syncthreads();

    // ---- stable first-<=5 active selection via ballots (f = tr*13 + c) ----
    int f0 = lane, f1 = 32 + lane;
    int tr0 = f0 / 13, c0 = f0 - tr0 * 13;
    int tr1 = f1 / 13, c1 = f1 - tr1 * 13;
    unsigned b0 = __ballot_sync(0xffffffffu, s_tgt[tr0 * 65 + c0] != 0.0f);
    unsigned b1 = __ballot_sync(0xffffffffu, s_tgt[tr1 * 65 + c1] != 0.0f);
    int act64 = (s_tgt[4 * 65 + 12] != 0.0f) ? 1 : 0;   // f = 64
    unsigned long long bits = (unsigned long long)b0 |
                              ((unsigned long long)b1 << 32);
    int total = __popcll(bits) + act64;
    const int v = (total < 5) ? total : 5;

    // fsel on lanes 0..4 (others compute lane-0 copy), broadcast via shfl
    int fsel = 0;
    {
        int sl = (lane < 5) ? lane : 0;
        if (sl < v) {
            if (sl < __popcll(bits)) {
                unsigned long long t = bits;
#pragma unroll
                for (int j = 0; j < 4; j++)
                    if (j < sl) t &= t - 1;
                fsel = __ffsll((long long)t) - 1;
            } else {
                fsel = 64;
            }
        }
    }

    // ---- TDOA class per (slot, pair): 30 lanes ----
    {
        int s  = lane / 6;               // slot (lane<30)
        int pr = lane - s * 6;           // pair
        int f  = __shfl_sync(0xffffffffu, fsel, (s < 5) ? s : 0);
        if (lane < 30) {
            int cls = 0;
            if (s < v) {
                const int pa[6]  = {0, 0, 0, 1, 1, 2};
                const int pbx[6] = {1, 2, 3, 2, 3, 3};
                int tr = f / 13, c = f - tr * 13;
                float dist = s_tgt[tr * 65 + 52 + c];
                float sx = __fmul_rn(s_tgt[tr * 65 + 13 + c], dist);
                float sy = __fmul_rn(s_tgt[tr * 65 + 26 + c], dist);
                float sz = __fmul_rn(s_tgt[tr * 65 + 39 + c], dist);
                int ma = pa[pr], mb = pbx[pr];
                float dxa = __fsub_rn(sx, s_mics[ma * 3 + 0]);
                float dya = __fsub_rn(sy, s_mics[ma * 3 + 1]);
                float dza = __fsub_rn(sz, s_mics[ma * 3 + 2]);
                float dxb = __fsub_rn(sx, s_mics[mb * 3 + 0]);
                float dyb = __fsub_rn(sy, s_mics[mb * 3 + 1]);
                float dzb = __fsub_rn(sz, s_mics[mb * 3 + 2]);
                float qa = __fadd_rn(__fadd_rn(__fmul_rn(dxa, dxa), __fmul_rn(dya, dya)), __fmul_rn(dza, dza));
                float qb = __fadd_rn(__fadd_rn(__fmul_rn(dxb, dxb), __fmul_rn(dyb, dyb)), __fmul_rn(dzb, dzb));
                float tdoa = __fsub_rn(__fsqrt_rn(qa), __fsqrt_rn(qb));
                cls = (int)rintf(__fdiv_rn(__fmul_rn(tdoa, 24000.0f), 343.0f)) + 6;
            }
            s_cls[w][s * 6 + pr] = (unsigned char)cls;
        }
    }
    __syncwarp();

    // ---- log-softmax per (pair, track): 30 lanes, register-lean ----
    if (lane < 30) {
        const int pair  = lane / 5;
        const int track = lane - pair * 5;
        const float* xp = &s_pred[w][track * 6 + pair];   // stride 30

        float mx = -FLT_MAX;
        int   am = 0;
#pragma unroll
        for (int cl = 0; cl < 13; cl++) {
            float x = xp[cl * 30];
            if (x > mx) { mx = x; am = cl; }   // first-occurrence argmax
        }
        // XLA GPU 32-lane column-reduction tree (leaves 13..31 == 0)
        float t0 = __fadd_rn(__nv_expf(__fsub_rn(xp[0],      mx)), __nv_expf(__fsub_rn(xp[8 * 30],  mx)));
        float t1 = __fadd_rn(__nv_expf(__fsub_rn(xp[1 * 30], mx)), __nv_expf(__fsub_rn(xp[9 * 30],  mx)));
        float t2 = __fadd_rn(__nv_expf(__fsub_rn(xp[2 * 30], mx)), __nv_expf(__fsub_rn(xp[10 * 30], mx)));
        float t3 = __fadd_rn(__nv_expf(__fsub_rn(xp[3 * 30], mx)), __nv_expf(__fsub_rn(xp[11 * 30], mx)));
        float t4 = __fadd_rn(__nv_expf(__fsub_rn(xp[4 * 30], mx)), __nv_expf(__fsub_rn(xp[12 * 30], mx)));
        float u0 = __fadd_rn(t0, t4);
        float u1 = __fadd_rn(t1, __nv_expf(__fsub_rn(xp[5 * 30], mx)));
        float u2 = __fadd_rn(t2, __nv_expf(__fsub_rn(xp[6 * 30], mx)));
        float u3 = __fadd_rn(t3, __nv_expf(__fsub_rn(xp[7 * 30], mx)));
        float sm = __fadd_rn(__fadd_rn(u0, u2), __fadd_rn(u1, u3));
        float lse = __nv_logf(sm);
        s_pc[w][pair * 5 + track] = (unsigned char)am;
        float vals[5];
#pragma unroll
        for (int k = 0; k < 5; k++) {
            int idx = (k < v) ? (int)s_cls[w][k * 6 + pair] : 0;
            float xv = xp[idx * 30];
            vals[k] = (k < v) ? __fsub_rn(lse, __fsub_rn(xv, mx)) : 0.0f;
        }
        __syncwarp(0x3fffffffu);   // s_tgt fully dead before lm overwrite
#pragma unroll
        for (int k = 0; k < 5; k++)
            s_lm[pair * 25 + k * 5 + track] = vals[k];
    }
    __syncwarp();

    // ---- build T13[pair][p1][p3] = fadd(lm1[p1], lm3[p3]) (exact tree op) ----
#pragma unroll
    for (int e = lane; e < 150; e += 32) {
        int pr = e / 25, r = e - pr * 25;
        int i = r / 5, j = r - i * 5;
        s_t13[e] = __fadd_rn(s_lm[pr * 25 + 5 + i], s_lm[pr * 25 + 15 + j]);
    }
    __syncwarp();

    // ---- perm argmin: group g (5 lanes) owns pair g; lane lig owns the
    // contiguous block pe in [24*lig, 24*lig+24); a0 = lm[lig] loop-invariant.
    // Zero rows (slot k >= v) make perms sharing a v-prefix bitwise-equal
    // (lm > 0 valid, +0 pads), so only block starts pe = pe0 + j*fac are
    // evaluated: cnt = {1,1,4,12,24,24}[v]. Two ascending chains + lazy
    // division reproduce reference first-occurrence argmin bitwise.
    const int g   = (lane < 30) ? (lane / 5) : 6;
    const int lig = lane - g * 5;     // == p0 for g < 6
    const char* lmB  = (const char*)(s_lm  + g * 25);
    const char* t13B = (const char*)(s_t13 + g * 25);

    const int fac = (v >= 4) ? 1 : ((v == 3) ? 2 : ((v == 2) ? 6 : 24));
    const int cnt = (g >= 6) ? 0 : ((v >= 4) ? 24 : ((v == 3) ? 12 : ((v == 2) ? 4 : 1)));
    const int pe0 = lig * 24;
    const float a0 = (g < 6) ? ((const float*)lmB)[lig] : 0.0f;
    const int half = (cnt + 1) >> 1;

    float bs0A = FLT_MAX, bcA = FLT_MAX;  int biA = 1 << 20;
    float bs0B = FLT_MAX, bcB = FLT_MAX;  int biB = 1 << 20;
    int peA = pe0;
    int peB = pe0 + half * fac;
#pragma unroll 1
    for (int jj = 0; jj < half; jj++) {
        {   // chain A (pe ascending)
            unsigned ep = s_ep2[peA];
            float y  = *(const float*)(t13B + (ep & 255u));          // a1+a3
            float a2 = *(const float*)(lmB + ((ep >> 8) & 255u));
            float a4 = *(const float*)(lmB + (ep >> 16));
            float s0 = __fadd_rn(__fadd_rn(__fadd_rn(a0, a4), a2), y);
            if (s0 < bs0A) {
                float cst = __fdiv_rn(s0, 5.0f);
                if (cst < bcA) { bcA = cst; biA = peA; }
                bs0A = s0;
            }
        }
        if (jj + half < cnt) {   // chain B (pe ascending)
            unsigned ep = s_ep2[peB];
            float y  = *(const float*)(t13B + (ep & 255u));
            float a2 = *(const float*)(lmB + ((ep >> 8) & 255u));
            float a4 = *(const float*)(lmB + (ep >> 16));
            float s0 = __fadd_rn(__fadd_rn(__fadd_rn(a0, a4), a2), y);
            if (s0 < bs0B) {
                float cst = __fdiv_rn(s0, 5.0f);
                if (cst < bcB) { bcB = cst; biB = peB; }
                bs0B = s0;
            }
        }
        peA += fac;
        peB += fac;
    }
    float bcst = bcA; int bidx = biA;
    if (bcB < bcst || (bcB == bcst && biB < bidx)) { bcst = bcB; bidx = biB; }

    // group reduce over 5 lanes (offsets 4,2,1, guarded)
#pragma unroll
    for (int off = 4; off; off >>= 1) {
        float ov = __shfl_down_sync(0xffffffffu, bcst, off);
        int   oi = __shfl_down_sync(0xffffffffu, bidx, off);
        if (lig + off < 5 && g < 6) {
            if (ov < bcst || (ov == bcst && oi < bidx)) { bcst = ov; bidx = oi; }
        }
    }

    // group leaders: accuracy count + stash results
    if (g < 6 && lig == 0) {
        int d[5];
        perm_digits(bidx, d);
        int corr = 0;
#pragma unroll
        for (int i = 0; i < 5; i++) {
            int s = d[i];   // tgt_perm[i] = tgt[perm[i]]
            if (s < v && (int)s_pc[w][g * 5 + i] == (int)s_cls[w][s * 6 + g]) corr++;
        }
        s_gl[w][g] = bcst;
        s_gc[w][g] = corr;
    }
    __syncwarp();

    if (lane == 0) {
        double wl = 0.0;
        int    wc = 0;
#pragma unroll
        for (int gg = 0; gg < 6; gg++) {
            wl += (double)s_gl[w][gg];
            wc += s_gc[w][gg];
        }
        s_wl[w] = wl;
        s_wc[w] = wc;
        s_wn[w] = 6 * v;
    }
    __syncthreads();

    // ---- block accumulate -> buckets; last block finalizes output ----
    if (tid == 0) {
        double L = 0.0;
        int    C = 0, NP = 0;
#pragma unroll
        for (int i = 0; i < WPB; i++) { L += s_wl[i]; C += s_wc[i]; NP += s_wn[i]; }
        int bk = blockIdx.x & (NBUCK - 1);
        atomicAdd(&g_bl[bk], L);
        atomicAdd(&g_bc[bk], (unsigned long long)C);
        atomicAdd(&g_bn[bk], (unsigned long long)NP);
        __threadfence();
    }
    if (w == 0) {
        unsigned t = 0;
        if (lane == 0) t = atomicInc(&g_cnt, NBLK - 1);  // wraps -> clean state
        t = __shfl_sync(0xffffffffu, t, 0);
        if (t == NBLK - 1) {
            double             L = g_bl[lane];
            unsigned long long C = g_bc[lane];
            unsigned long long N = g_bn[lane];
            g_bl[lane] = 0.0;    // re-zero for next replay
            g_bc[lane] = 0ull;
            g_bn[lane] = 0ull;
#pragma unroll
            for (int off = 16; off; off >>= 1) {
                L += __shfl_down_sync(0xffffffffu, L, off);
                C += __shfl_down_sync(0xffffffffu, C, off);
                N += __shfl_down_sync(0xffffffffu, N, off);
            }
            if (lane == 0) {
                if (nout >= 1) out[0] = (float)(L / 192000.0);
                if (nout >= 2) out[1] = (N > 0) ? (float)((double)C / (double)N) : 0.0f;
            }
        }
    }
}

extern "C" void kernel_launch(void* const* d_in, const int* in_sizes, int n_in,
                              void* d_out, int out_size) {
    const float* pred   = (const float*)d_in[0];
    const float* target = (const float*)d_in[1];
    const float* mics   = (const float*)d_in[2];
    (void)in_sizes; (void)n_in;

    tdoa_main<<<NBLK, 256>>>(pred, target, mics, (float*)d_out, out_size);
}

// round 13
// speedup vs baseline: 1.2695x; 1.0014x over previous
#include <cuda_runtime.h>
#include <math.h>
#include <float.h>

// Accurate libdevice math (same routines XLA GPU lowers f32 exp/log to).
extern "C" __device__ float __nv_expf(float);
extern "C" __device__ float __nv_logf(float);

// B=64, T=500 -> 32000 (b,t) rows; NLOGIT=13, TR=5, P=6 pairs.
// pred  : (64,500,13,5,6) f32 -> 390 floats per (b,t)
// target: (64,500,5,5,13) f32 -> 325 floats per (b,t)
// mic_locs: (4,3) f32 ; out: [loss, acc] f32
//
// 256 threads = 8 warps, one (b,t) row per warp.
// Perm-argmin: 6 groups of 5 lanes; group g owns mic-pair g; lane lig owns
// the contiguous perm block pe in [24*lig, 24*lig+24) (first digit p0 = lig).
// Cost tree ((a0+a4)+a2)+(a1+a3): the (a1+a3) term is precomputed per pair
// into T13[25] (bitwise the same fadd), so each eval is 3 LDS + 3 FADD.

#define NBT    32000
#define WPB    8
#define NBLK   (NBT / WPB)   // 4000
#define NBUCK  32

__device__ double             g_bl[NBUCK];   // zero-init; last block re-zeroes
__device__ unsigned long long g_bc[NBUCK];
__device__ unsigned long long g_bn[NBUCK];
__device__ unsigned           g_cnt;         // wraps to 0 every full launch

// Lexicographic (itertools) perm index -> digits d[0..4].
__device__ __forceinline__ void perm_digits(int p, int* d) {
    int avail[5] = {0, 1, 2, 3, 4};
    const int fact[4] = {24, 6, 2, 1};
#pragma unroll
    for (int i = 0; i < 4; i++) {
        int q = p / fact[i];
        p -= q * fact[i];
        d[i] = avail[q];
#pragma unroll
        for (int j = 0; j < 4; j++)
            if (j >= q) avail[j] = avail[j + 1];
    }
    d[4] = avail[0];
}

__global__ __launch_bounds__(256, 8) void tdoa_main(
    const float* __restrict__ pred,
    const float* __restrict__ target,
    const float* __restrict__ mics,
    float* __restrict__ out, int nout)
{
    __shared__ __align__(16) float s_pred[WPB][390];  // cl*30 + track*6 + pair
    // Overlay: phase 1 = s_tgt (325 f); phase 2 = s_lm (150 f) + T13 (150 f).
    __shared__ __align__(16) float s_u[WPB][325];
    __shared__ unsigned char s_cls[WPB][32];   // slot*6 + pair
    __shared__ unsigned char s_pc[WPB][32];    // pair*5 + track
    // Packed byte-offsets per perm: b0=4*(p1*5+p3), b1=4*(10+p2), b2=4*(20+p4)
    __shared__ unsigned s_ep2[128];            // [120..127] = 0
    __shared__ float    s_mics[12];
    __shared__ float    s_gl[WPB][6];          // per-group best cost
    __shared__ int      s_gc[WPB][6];          // per-group correct count
    __shared__ double   s_wl[WPB];
    __shared__ int      s_wc[WPB], s_wn[WPB];

    const int tid  = threadIdx.x;
    const int w    = tid >> 5;
    const int lane = tid & 31;
    const int bt   = blockIdx.x * WPB + w;

    float* s_tgt = s_u[w];           // phase 1
    float* s_lm  = s_u[w];           // phase 2: [0..149]  pair*25 + slot*5 + track
    float* s_t13 = s_u[w] + 150;     // phase 2: [150..299] pair*25 + p1*5 + p3

    // ---- stage inputs + block tables ----
    {
        const float2* pb2 = (const float2*)(pred + (size_t)bt * 390u); // even -> 8B aligned
        float2* sp2 = (float2*)&s_pred[w][0];
#pragma unroll
        for (int i = 0; i < 6; i++) sp2[lane + 32 * i] = pb2[lane + 32 * i];
        if (lane < 3) sp2[192 + lane] = pb2[192 + lane];
        const float* tb = target + (size_t)bt * 325u;
        for (int i = lane; i < 325; i += 32) s_tgt[i] = tb[i];
    }
    if (tid < 128) {
        unsigned ep = 0;
        if (tid < 120) {
            int d[5];
            perm_digits(tid, d);
            ep  = (unsigned)(4 * (d[1] * 5 + d[3]));
            ep |= (unsigned)(4 * (10 + d[2])) << 8;
            ep |= (unsigned)(4 * (20 + d[4])) << 16;
        }
        s_ep2[tid] = ep;
    }
    if (tid < 12) s_mics[tid] = mics[tid];
    __syncthreads();

    // ---- stable first-<=5 active selection via ballots (f = tr*13 + c) ----
    int f0 = lane, f1 = 32 + lane;
    int tr0 = f0 / 13, c0 = f0 - tr0 * 13;
    int tr1 = f1 / 13, c1 = f1 - tr1 * 13;
    unsigned b0 = __ballot_sync(0xffffffffu, s_tgt[tr0 * 65 + c0] != 0.0f);
    unsigned b1 = __ballot_sync(0xffffffffu, s_tgt[tr1 * 65 + c1] != 0.0f);
    int act64 = (s_tgt[4 * 65 + 12] != 0.0f) ? 1 : 0;   // f = 64
    unsigned long long bits = (unsigned long long)b0 |
                              ((unsigned long long)b1 << 32);
    int total = __popcll(bits) + act64;
    const int v = (total < 5) ? total : 5;

    // fsel on lanes 0..4 (others compute lane-0 copy), broadcast via shfl
    int fsel = 0;
    {
        int sl = (lane < 5) ? lane : 0;
        if (sl < v) {
            if (sl < __popcll(bits)) {
                unsigned long long t = bits;
#pragma unroll
                for (int j = 0; j < 4; j++)
                    if (j < sl) t &= t - 1;
                fsel = __ffsll((long long)t) - 1;
            } else {
                fsel = 64;
            }
        }
    }

    // ---- TDOA class per (slot, pair): 30 lanes ----
    {
        int s  = lane / 6;               // slot (lane<30)
        int pr = lane - s * 6;           // pair
        int f  = __shfl_sync(0xffffffffu, fsel, (s < 5) ? s : 0);
        if (lane < 30) {
            int cls = 0;
            if (s < v) {
                const int pa[6]  = {0, 0, 0, 1, 1, 2};
                const int pbx[6] = {1, 2, 3, 2, 3, 3};
                int tr = f / 13, c = f - tr * 13;
                float dist = s_tgt[tr * 65 + 52 + c];
                float sx = __fmul_rn(s_tgt[tr * 65 + 13 + c], dist);
                float sy = __fmul_rn(s_tgt[tr * 65 + 26 + c], dist);
                float sz = __fmul_rn(s_tgt[tr * 65 + 39 + c], dist);
                int ma = pa[pr], mb = pbx[pr];
                float dxa = __fsub_rn(sx, s_mics[ma * 3 + 0]);
                float dya = __fsub_rn(sy, s_mics[ma * 3 + 1]);
                float dza = __fsub_rn(sz, s_mics[ma * 3 + 2]);
                float dxb = __fsub_rn(sx, s_mics[mb * 3 + 0]);
                float dyb = __fsub_rn(sy, s_mics[mb * 3 + 1]);
                float dzb = __fsub_rn(sz, s_mics[mb * 3 + 2]);
                float qa = __fadd_rn(__fadd_rn(__fmul_rn(dxa, dxa), __fmul_rn(dya, dya)), __fmul_rn(dza, dza));
                float qb = __fadd_rn(__fadd_rn(__fmul_rn(dxb, dxb), __fmul_rn(dyb, dyb)), __fmul_rn(dzb, dzb));
                float tdoa = __fsub_rn(__fsqrt_rn(qa), __fsqrt_rn(qb));
                cls = (int)rintf(__fdiv_rn(__fmul_rn(tdoa, 24000.0f), 343.0f)) + 6;
            }
            s_cls[w][s * 6 + pr] = (unsigned char)cls;
        }
    }
    __syncwarp();

    // ---- log-softmax per (pair, track): 30 lanes, register-lean ----
    if (lane < 30) {
        const int pair  = lane / 5;
        const int track = lane - pair * 5;
        const float* xp = &s_pred[w][track * 6 + pair];   // stride 30

        float mx = -FLT_MAX;
        int   am = 0;
#pragma unroll
        for (int cl = 0; cl < 13; cl++) {
            float x = xp[cl * 30];
            if (x > mx) { mx = x; am = cl; }   // first-occurrence argmax
        }
        // XLA GPU 32-lane column-reduction tree (leaves 13..31 == 0)
        float t0 = __fadd_rn(__nv_expf(__fsub_rn(xp[0],      mx)), __nv_expf(__fsub_rn(xp[8 * 30],  mx)));
        float t1 = __fadd_rn(__nv_expf(__fsub_rn(xp[1 * 30], mx)), __nv_expf(__fsub_rn(xp[9 * 30],  mx)));
        float t2 = __fadd_rn(__nv_expf(__fsub_rn(xp[2 * 30], mx)), __nv_expf(__fsub_rn(xp[10 * 30], mx)));
        float t3 = __fadd_rn(__nv_expf(__fsub_rn(xp[3 * 30], mx)), __nv_expf(__fsub_rn(xp[11 * 30], mx)));
        float t4 = __fadd_rn(__nv_expf(__fsub_rn(xp[4 * 30], mx)), __nv_expf(__fsub_rn(xp[12 * 30], mx)));
        float u0 = __fadd_rn(t0, t4);
        float u1 = __fadd_rn(t1, __nv_expf(__fsub_rn(xp[5 * 30], mx)));
        float u2 = __fadd_rn(t2, __nv_expf(__fsub_rn(xp[6 * 30], mx)));
        float u3 = __fadd_rn(t3, __nv_expf(__fsub_rn(xp[7 * 30], mx)));
        float sm = __fadd_rn(__fadd_rn(u0, u2), __fadd_rn(u1, u3));
        float lse = __nv_logf(sm);
        s_pc[w][pair * 5 + track] = (unsigned char)am;
        float vals[5];
#pragma unroll
        for (int k = 0; k < 5; k++) {
            int idx = (k < v) ? (int)s_cls[w][k * 6 + pair] : 0;
            float xv = xp[idx * 30];
            vals[k] = (k < v) ? __fsub_rn(lse, __fsub_rn(xv, mx)) : 0.0f;
        }
        __syncwarp(0x3fffffffu);   // s_tgt fully dead before lm overwrite
#pragma unroll
        for (int k = 0; k < 5; k++)
            s_lm[pair * 25 + k * 5 + track] = vals[k];
    }
    __syncwarp();

    // ---- build T13[pair][p1][p3] = fadd(lm1[p1], lm3[p3]) (exact tree op) ----
#pragma unroll
    for (int e = lane; e < 150; e += 32) {
        int pr = e / 25, r = e - pr * 25;
        int i = r / 5, j = r - i * 5;
        s_t13[e] = __fadd_rn(s_lm[pr * 25 + 5 + i], s_lm[pr * 25 + 15 + j]);
    }
    __syncwarp();

    // ---- perm argmin: group g (5 lanes) owns pair g; lane lig owns the
    // contiguous block pe in [24*lig, 24*lig+24); a0 = lm[lig] loop-invariant.
    // Zero rows (slot k >= v) make perms sharing a v-prefix bitwise-equal
    // (lm > 0 valid, +0 pads), so only block starts pe = pe0 + j*fac are
    // evaluated: cnt = {1,1,4,12,24,24}[v]. Two ascending chains + lazy
    // division reproduce reference first-occurrence argmin bitwise.
    const int g   = (lane < 30) ? (lane / 5) : 6;
    const int lig = lane - g * 5;     // == p0 for g < 6
    const char* lmB  = (const char*)(s_lm  + g * 25);
    const char* t13B = (const char*)(s_t13 + g * 25);

    const int fac = (v >= 4) ? 1 : ((v == 3) ? 2 : ((v == 2) ? 6 : 24));
    const int cnt = (g >= 6) ? 0 : ((v >= 4) ? 24 : ((v == 3) ? 12 : ((v == 2) ? 4 : 1)));
    const int pe0 = lig * 24;
    const float a0 = (g < 6) ? ((const float*)lmB)[lig] : 0.0f;
    const int half = (cnt + 1) >> 1;

    float bs0A = FLT_MAX, bcA = FLT_MAX;  int biA = 1 << 20;
    float bs0B = FLT_MAX, bcB = FLT_MAX;  int biB = 1 << 20;
    int peA = pe0;
    int peB = pe0 + half * fac;
#pragma unroll 1
    for (int jj = 0; jj < half; jj++) {
        {   // chain A (pe ascending)
            unsigned ep = s_ep2[peA];
            float y  = *(const float*)(t13B + (ep & 255u));          // a1+a3
            float a2 = *(const float*)(lmB + ((ep >> 8) & 255u));
            float a4 = *(const float*)(lmB + (ep >> 16));
            float s0 = __fadd_rn(__fadd_rn(__fadd_rn(a0, a4), a2), y);
            if (s0 < bs0A) {
                float cst = __fdiv_rn(s0, 5.0f);
                if (cst < bcA) { bcA = cst; biA = peA; }
                bs0A = s0;
            }
        }
        if (jj + half < cnt) {   // chain B (pe ascending)
            unsigned ep = s_ep2[peB];
            float y  = *(const float*)(t13B + (ep & 255u));
            float a2 = *(const float*)(lmB + ((ep >> 8) & 255u));
            float a4 = *(const float*)(lmB + (ep >> 16));
            float s0 = __fadd_rn(__fadd_rn(__fadd_rn(a0, a4), a2), y);
            if (s0 < bs0B) {
                float cst = __fdiv_rn(s0, 5.0f);
                if (cst < bcB) { bcB = cst; biB = peB; }
                bs0B = s0;
            }
        }
        peA += fac;
        peB += fac;
    }
    float bcst = bcA; int bidx = biA;
    if (bcB < bcst || (bcB == bcst && biB < bidx)) { bcst = bcB; bidx = biB; }

    // group reduce over 5 lanes (offsets 4,2,1, guarded)
#pragma unroll
    for (int off = 4; off; off >>= 1) {
        float ov = __shfl_down_sync(0xffffffffu, bcst, off);
        int   oi = __shfl_down_sync(0xffffffffu, bidx, off);
        if (lig + off < 5 && g < 6) {
            if (ov < bcst || (ov == bcst && oi < bidx)) { bcst = ov; bidx = oi; }
        }
    }

    // group leaders: accuracy count + stash results
    if (g < 6 && lig == 0) {
        int d[5];
        perm_digits(bidx, d);
        int corr = 0;
#pragma unroll
        for (int i = 0; i < 5; i++) {
            int s = d[i];   // tgt_perm[i] = tgt[perm[i]]
            if (s < v && (int)s_pc[w][g * 5 + i] == (int)s_cls[w][s * 6 + g]) corr++;
        }
        s_gl[w][g] = bcst;
        s_gc[w][g] = corr;
    }
    __syncwarp();

    if (lane == 0) {
        double wl = 0.0;
        int    wc = 0;
#pragma unroll
        for (int gg = 0; gg < 6; gg++) {
            wl += (double)s_gl[w][gg];
            wc += s_gc[w][gg];
        }
        s_wl[w] = wl;
        s_wc[w] = wc;
        s_wn[w] = 6 * v;
    }
    __syncthreads();

    // ---- block accumulate -> buckets; last block finalizes output ----
    if (tid == 0) {
        double L = 0.0;
        int    C = 0, NP = 0;
#pragma unroll
        for (int i = 0; i < WPB; i++) { L += s_wl[i]; C += s_wc[i]; NP += s_wn[i]; }
        int bk = blockIdx.x & (NBUCK - 1);
        atomicAdd(&g_bl[bk], L);
        atomicAdd(&g_bc[bk], (unsigned long long)C);
        atomicAdd(&g_bn[bk], (unsigned long long)NP);
        __threadfence();
    }
    if (w == 0) {
        unsigned t = 0;
        if (lane == 0) t = atomicInc(&g_cnt, NBLK - 1);  // wraps -> clean state
        t = __shfl_sync(0xffffffffu, t, 0);
        if (t == NBLK - 1) {
            double             L = g_bl[lane];
            unsigned long long C = g_bc[lane];
            unsigned long long N = g_bn[lane];
            g_bl[lane] = 0.0;    // re-zero for next replay
            g_bc[lane] = 0ull;
            g_bn[lane] = 0ull;
#pragma unroll
            for (int off = 16; off; off >>= 1) {
                L += __shfl_down_sync(0xffffffffu, L, off);
                C += __shfl_down_sync(0xffffffffu, C, off);
                N += __shfl_down_sync(0xffffffffu, N, off);
            }
            if (lane == 0) {
                if (nout >= 1) out[0] = (float)(L / 192000.0);
                if (nout >= 2) out[1] = (N > 0) ? (float)((double)C / (double)N) : 0.0f;
            }
        }
    }
}

extern "C" void kernel_launch(void* const* d_in, const int* in_sizes, int n_in,
                              void* d_out, int out_size) {
    const float* pred   = (const float*)d_in[0];
    const float* target = (const float*)d_in[1];
    const float* mics   = (const float*)d_in[2];
    (void)in_sizes; (void)n_in;

    tdoa_main<<<NBLK, 256>>>(pred, target, mics, (float*)d_out, out_size);
}

// round 14
// speedup vs baseline: 1.2971x; 1.0217x over previous
#include <cuda_runtime.h>
#include <math.h>
#include <float.h>

// Accurate libdevice math (same routines XLA GPU lowers f32 exp/log to).
extern "C" __device__ float __nv_expf(float);
extern "C" __device__ float __nv_logf(float);

// B=64, T=500 -> 32000 (b,t) rows; NLOGIT=13, TR=5, P=6 pairs.
// pred  : (64,500,13,5,6) f32 -> 390 floats per (b,t)
// target: (64,500,5,5,13) f32 -> 325 floats per (b,t)
// mic_locs: (4,3) f32 ; out: [loss, acc] f32
//
// 256 threads = 8 warps, one (b,t) row per warp.
// Perm-argmin: 6 groups of 5 lanes; group g owns mic-pair g; lane lig owns
// the contiguous perm block pe in [24*lig, 24*lig+24) (first digit p0 = lig).
// Cost tree ((a0+a4)+a2)+(a1+a3): (a1+a3) precomputed per pair into T13[25]
// (bitwise the same fadd). Scan specialized per warp-uniform v and fully
// unrolled (immediate LDS offsets, no loop overhead).

#define NBT    32000
#define WPB    8
#define NBLK   (NBT / WPB)   // 4000
#define NBUCK  32

__device__ double             g_bl[NBUCK];   // zero-init; last block re-zeroes
__device__ unsigned long long g_bc[NBUCK];
__device__ unsigned long long g_bn[NBUCK];
__device__ unsigned           g_cnt;         // wraps to 0 every full launch

// Lexicographic (itertools) perm index -> digits d[0..4].
__device__ __forceinline__ void perm_digits(int p, int* d) {
    int avail[5] = {0, 1, 2, 3, 4};
    const int fact[4] = {24, 6, 2, 1};
#pragma unroll
    for (int i = 0; i < 4; i++) {
        int q = p / fact[i];
        p -= q * fact[i];
        d[i] = avail[q];
#pragma unroll
        for (int j = 0; j < 4; j++)
            if (j >= q) avail[j] = avail[j + 1];
    }
    d[4] = avail[0];
}

// Fully-unrolled two-chain lazy-division scan over block starts
// pe = pe0 + j*FAC, j in [0, CNT). Exact first-occurrence argmin of
// div(s0,5) in ascending-pe order (div only on strict raw improvement;
// divided-tie keeps the earlier index).
template<int CNT, int FAC>
__device__ __forceinline__ void pscan(
    const unsigned* __restrict__ s_ep2,
    const char* __restrict__ lmB, const char* __restrict__ t13B,
    float a0, int pe0, float& bcst_o, int& bidx_o)
{
    constexpr int HALF = (CNT + 1) / 2;
    float bs0A = FLT_MAX, bcA = FLT_MAX;  int biA = 1 << 20;
    float bs0B = FLT_MAX, bcB = FLT_MAX;  int biB = 1 << 20;
#pragma unroll
    for (int jj = 0; jj < HALF; jj++) {
        {   // chain A (pe ascending)
            int pe = pe0 + jj * FAC;
            unsigned ep = s_ep2[pe];
            float y  = *(const float*)(t13B + (ep & 255u));          // a1+a3
            float a2 = *(const float*)(lmB + ((ep >> 8) & 255u));
            float a4 = *(const float*)(lmB + (ep >> 16));
            float s0 = __fadd_rn(__fadd_rn(__fadd_rn(a0, a4), a2), y);
            if (s0 < bs0A) {
                float cst = __fdiv_rn(s0, 5.0f);
                if (cst < bcA) { bcA = cst; biA = pe; }
                bs0A = s0;
            }
        }
        if (jj + HALF < CNT) {   // chain B (pe ascending), compile-time bound
            int pe = pe0 + (jj + HALF) * FAC;
            unsigned ep = s_ep2[pe];
            float y  = *(const float*)(t13B + (ep & 255u));
            float a2 = *(const float*)(lmB + ((ep >> 8) & 255u));
            float a4 = *(const float*)(lmB + (ep >> 16));
            float s0 = __fadd_rn(__fadd_rn(__fadd_rn(a0, a4), a2), y);
            if (s0 < bs0B) {
                float cst = __fdiv_rn(s0, 5.0f);
                if (cst < bcB) { bcB = cst; biB = pe; }
                bs0B = s0;
            }
        }
    }
    float bc = bcA; int bi = biA;
    if (bcB < bc || (bcB == bc && biB < bi)) { bc = bcB; bi = biB; }
    bcst_o = bc; bidx_o = bi;
}

__global__ __launch_bounds__(256, 8) void tdoa_main(
    const float* __restrict__ pred,
    const float* __restrict__ target,
    const float* __restrict__ mics,
    float* __restrict__ out, int nout)
{
    __shared__ __align__(16) float s_pred[WPB][390];  // cl*30 + track*6 + pair
    // Overlay: phase 1 = s_tgt (325 f); phase 2 = s_lm (150 f) + T13 (150 f).
    __shared__ __align__(16) float s_u[WPB][325];
    __shared__ unsigned char s_cls[WPB][32];   // slot*6 + pair
    __shared__ unsigned char s_pc[WPB][32];    // pair*5 + track
    // Packed byte-offsets per perm: b0=4*(p1*5+p3), b1=4*(10+p2), b2=4*(20+p4)
    __shared__ unsigned s_ep2[128];            // [120..127] = 0
    __shared__ float    s_mics[12];
    __shared__ float    s_gl[WPB][6];          // per-group best cost
    __shared__ int      s_gc[WPB][6];          // per-group correct count
    __shared__ double   s_wl[WPB];
    __shared__ int      s_wc[WPB], s_wn[WPB];

    const int tid  = threadIdx.x;
    const int w    = tid >> 5;
    const int lane = tid & 31;
    const int bt   = blockIdx.x * WPB + w;

    float* s_tgt = s_u[w];           // phase 1
    float* s_lm  = s_u[w];           // phase 2: [0..149]  pair*25 + slot*5 + track
    float* s_t13 = s_u[w] + 150;     // phase 2: [150..299] pair*25 + p1*5 + p3

    // ---- stage inputs + block tables ----
    {
        const float2* pb2 = (const float2*)(pred + (size_t)bt * 390u); // even -> 8B aligned
        float2* sp2 = (float2*)&s_pred[w][0];
#pragma unroll
        for (int i = 0; i < 6; i++) sp2[lane + 32 * i] = pb2[lane + 32 * i];
        if (lane < 3) sp2[192 + lane] = pb2[192 + lane];
        const float* tb = target + (size_t)bt * 325u;
        for (int i = lane; i < 325; i += 32) s_tgt[i] = tb[i];
    }
    if (tid < 128) {
        unsigned ep = 0;
        if (tid < 120) {
            int d[5];
            perm_digits(tid, d);
            ep  = (unsigned)(4 * (d[1] * 5 + d[3]));
            ep |= (unsigned)(4 * (10 + d[2])) << 8;
            ep |= (unsigned)(4 * (20 + d[4])) << 16;
        }
        s_ep2[tid] = ep;
    }
    if (tid < 12) s_mics[tid] = mics[tid];
    __syncthreads();

    // ---- stable first-<=5 active selection via ballots (f = tr*13 + c) ----
    int f0 = lane, f1 = 32 + lane;
    int tr0 = f0 / 13, c0 = f0 - tr0 * 13;
    int tr1 = f1 / 13, c1 = f1 - tr1 * 13;
    unsigned b0 = __ballot_sync(0xffffffffu, s_tgt[tr0 * 65 + c0] != 0.0f);
    unsigned b1 = __ballot_sync(0xffffffffu, s_tgt[tr1 * 65 + c1] != 0.0f);
    int act64 = (s_tgt[4 * 65 + 12] != 0.0f) ? 1 : 0;   // f = 64
    unsigned long long bits = (unsigned long long)b0 |
                              ((unsigned long long)b1 << 32);
    int total = __popcll(bits) + act64;
    const int v = (total < 5) ? total : 5;

    // fsel on lanes 0..4 (others compute lane-0 copy), broadcast via shfl
    int fsel = 0;
    {
        int sl = (lane < 5) ? lane : 0;
        if (sl < v) {
            if (sl < __popcll(bits)) {
                unsigned long long t = bits;
#pragma unroll
                for (int j = 0; j < 4; j++)
                    if (j < sl) t &= t - 1;
                fsel = __ffsll((long long)t) - 1;
            } else {
                fsel = 64;
            }
        }
    }

    // ---- TDOA class per (slot, pair): 30 lanes ----
    {
        int s  = lane / 6;               // slot (lane<30)
        int pr = lane - s * 6;           // pair
        int f  = __shfl_sync(0xffffffffu, fsel, (s < 5) ? s : 0);
        if (lane < 30) {
            int cls = 0;
            if (s < v) {
                const int pa[6]  = {0, 0, 0, 1, 1, 2};
                const int pbx[6] = {1, 2, 3, 2, 3, 3};
                int tr = f / 13, c = f - tr * 13;
                float dist = s_tgt[tr * 65 + 52 + c];
                float sx = __fmul_rn(s_tgt[tr * 65 + 13 + c], dist);
                float sy = __fmul_rn(s_tgt[tr * 65 + 26 + c], dist);
                float sz = __fmul_rn(s_tgt[tr * 65 + 39 + c], dist);
                int ma = pa[pr], mb = pbx[pr];
                float dxa = __fsub_rn(sx, s_mics[ma * 3 + 0]);
                float dya = __fsub_rn(sy, s_mics[ma * 3 + 1]);
                float dza = __fsub_rn(sz, s_mics[ma * 3 + 2]);
                float dxb = __fsub_rn(sx, s_mics[mb * 3 + 0]);
                float dyb = __fsub_rn(sy, s_mics[mb * 3 + 1]);
                float dzb = __fsub_rn(sz, s_mics[mb * 3 + 2]);
                float qa = __fadd_rn(__fadd_rn(__fmul_rn(dxa, dxa), __fmul_rn(dya, dya)), __fmul_rn(dza, dza));
                float qb = __fadd_rn(__fadd_rn(__fmul_rn(dxb, dxb), __fmul_rn(dyb, dyb)), __fmul_rn(dzb, dzb));
                float tdoa = __fsub_rn(__fsqrt_rn(qa), __fsqrt_rn(qb));
                cls = (int)rintf(__fdiv_rn(__fmul_rn(tdoa, 24000.0f), 343.0f)) + 6;
            }
            s_cls[w][s * 6 + pr] = (unsigned char)cls;
        }
    }
    __syncwarp();

    // ---- log-softmax per (pair, track): 30 lanes, register-lean ----
    if (lane < 30) {
        const int pair  = lane / 5;
        const int track = lane - pair * 5;
        const float* xp = &s_pred[w][track * 6 + pair];   // stride 30

        float mx = -FLT_MAX;
        int   am = 0;
#pragma unroll
        for (int cl = 0; cl < 13; cl++) {
            float x = xp[cl * 30];
            if (x > mx) { mx = x; am = cl; }   // first-occurrence argmax
        }
        // XLA GPU 32-lane column-reduction tree (leaves 13..31 == 0)
        float t0 = __fadd_rn(__nv_expf(__fsub_rn(xp[0],      mx)), __nv_expf(__fsub_rn(xp[8 * 30],  mx)));
        float t1 = __fadd_rn(__nv_expf(__fsub_rn(xp[1 * 30], mx)), __nv_expf(__fsub_rn(xp[9 * 30],  mx)));
        float t2 = __fadd_rn(__nv_expf(__fsub_rn(xp[2 * 30], mx)), __nv_expf(__fsub_rn(xp[10 * 30], mx)));
        float t3 = __fadd_rn(__nv_expf(__fsub_rn(xp[3 * 30], mx)), __nv_expf(__fsub_rn(xp[11 * 30], mx)));
        float t4 = __fadd_rn(__nv_expf(__fsub_rn(xp[4 * 30], mx)), __nv_expf(__fsub_rn(xp[12 * 30], mx)));
        float u0 = __fadd_rn(t0, t4);
        float u1 = __fadd_rn(t1, __nv_expf(__fsub_rn(xp[5 * 30], mx)));
        float u2 = __fadd_rn(t2, __nv_expf(__fsub_rn(xp[6 * 30], mx)));
        float u3 = __fadd_rn(t3, __nv_expf(__fsub_rn(xp[7 * 30], mx)));
        float sm = __fadd_rn(__fadd_rn(u0, u2), __fadd_rn(u1, u3));
        float lse = __nv_logf(sm);
        s_pc[w][pair * 5 + track] = (unsigned char)am;
        float vals[5];
#pragma unroll
        for (int k = 0; k < 5; k++) {
            int idx = (k < v) ? (int)s_cls[w][k * 6 + pair] : 0;
            float xv = xp[idx * 30];
            vals[k] = (k < v) ? __fsub_rn(lse, __fsub_rn(xv, mx)) : 0.0f;
        }
        __syncwarp(0x3fffffffu);   // s_tgt fully dead before lm overwrite
#pragma unroll
        for (int k = 0; k < 5; k++)
            s_lm[pair * 25 + k * 5 + track] = vals[k];
    }
    __syncwarp();

    // ---- build T13[pair][p1][p3] = fadd(lm1[p1], lm3[p3]) (exact tree op) ----
    // lane = pair*5 + p1 (30 lanes), linear addressing, 5 entries per lane.
    if (lane < 30) {
        const int pair = lane / 5;
        const int i    = lane - pair * 5;      // p1
        const float* lmp = s_lm + pair * 25;
        float lm1 = lmp[5 + i];
        float* dst = s_t13 + pair * 25 + i * 5;
#pragma unroll
        for (int j = 0; j < 5; j++)
            dst[j] = __fadd_rn(lm1, lmp[15 + j]);
    }
    __syncwarp();

    // ---- perm argmin: group g (5 lanes) owns pair g; lane lig owns the
    // contiguous block pe in [24*lig, 24*lig+24); a0 = lm[lig] loop-invariant.
    // Zero rows (slot k >= v) make perms sharing a v-prefix bitwise-equal
    // (lm > 0 valid, +0 pads), so only block starts pe = pe0 + j*fac are
    // evaluated: cnt = {1,1,4,12,24,24}[v]. v is warp-uniform -> branch into
    // fully-unrolled specializations.
    const int g   = (lane < 30) ? (lane / 5) : 6;
    const int gc6 = (g < 6) ? g : 5;          // clamp for safe addressing
    const int lig = lane - g * 5;             // == p0 for g < 6
    const char* lmB  = (const char*)(s_lm  + gc6 * 25);
    const char* t13B = (const char*)(s_t13 + gc6 * 25);
    const int pe0 = (g < 6) ? lig * 24 : 0;
    const float a0 = ((const float*)lmB)[(g < 6) ? lig : 0];

    float bcst;
    int   bidx;
    if (v >= 4)      pscan<24, 1>(s_ep2, lmB, t13B, a0, pe0, bcst, bidx);
    else if (v == 3) pscan<12, 2>(s_ep2, lmB, t13B, a0, pe0, bcst, bidx);
    else if (v == 2) pscan<4, 6>(s_ep2, lmB, t13B, a0, pe0, bcst, bidx);
    else             pscan<1, 24>(s_ep2, lmB, t13B, a0, pe0, bcst, bidx);

    // group reduce over 5 lanes (offsets 4,2,1, guarded)
#pragma unroll
    for (int off = 4; off; off >>= 1) {
        float ov = __shfl_down_sync(0xffffffffu, bcst, off);
        int   oi = __shfl_down_sync(0xffffffffu, bidx, off);
        if (lig + off < 5 && g < 6) {
            if (ov < bcst || (ov == bcst && oi < bidx)) { bcst = ov; bidx = oi; }
        }
    }

    // group leaders: accuracy count + stash results
    if (g < 6 && lig == 0) {
        int d[5];
        perm_digits(bidx, d);
        int corr = 0;
#pragma unroll
        for (int i = 0; i < 5; i++) {
            int s = d[i];   // tgt_perm[i] = tgt[perm[i]]
            if (s < v && (int)s_pc[w][g * 5 + i] == (int)s_cls[w][s * 6 + g]) corr++;
        }
        s_gl[w][g] = bcst;
        s_gc[w][g] = corr;
    }
    __syncwarp();

    if (lane == 0) {
        double wl = 0.0;
        int    wc = 0;
#pragma unroll
        for (int gg = 0; gg < 6; gg++) {
            wl += (double)s_gl[w][gg];
            wc += s_gc[w][gg];
        }
        s_wl[w] = wl;
        s_wc[w] = wc;
        s_wn[w] = 6 * v;
    }
    __syncthreads();

    // ---- block accumulate -> buckets; last block finalizes output ----
    if (tid == 0) {
        double L = 0.0;
        int    C = 0, NP = 0;
#pragma unroll
        for (int i = 0; i < WPB; i++) { L += s_wl[i]; C += s_wc[i]; NP += s_wn[i]; }
        int bk = blockIdx.x & (NBUCK - 1);
        atomicAdd(&g_bl[bk], L);
        atomicAdd(&g_bc[bk], (unsigned long long)C);
        atomicAdd(&g_bn[bk], (unsigned long long)NP);
        __threadfence();
    }
    if (w == 0) {
        unsigned t = 0;
        if (lane == 0) t = atomicInc(&g_cnt, NBLK - 1);  // wraps -> clean state
        t = __shfl_sync(0xffffffffu, t, 0);
        if (t == NBLK - 1) {
            double             L = g_bl[lane];
            unsigned long long C = g_bc[lane];
            unsigned long long N = g_bn[lane];
            g_bl[lane] = 0.0;    // re-zero for next replay
            g_bc[lane] = 0ull;
            g_bn[lane] = 0ull;
#pragma unroll
            for (int off = 16; off; off >>= 1) {
                L += __shfl_down_sync(0xffffffffu, L, off);
                C += __shfl_down_sync(0xffffffffu, C, off);
                N += __shfl_down_sync(0xffffffffu, N, off);
            }
            if (lane == 0) {
                if (nout >= 1) out[0] = (float)(L / 192000.0);
                if (nout >= 2) out[1] = (N > 0) ? (float)((double)C / (double)N) : 0.0f;
            }
        }
    }
}

extern "C" void kernel_launch(void* const* d_in, const int* in_sizes, int n_in,
                              void* d_out, int out_size) {
    const float* pred   = (const float*)d_in[0];
    const float* target = (const float*)d_in[1];
    const float* mics   = (const float*)d_in[2];
    (void)in_sizes; (void)n_in;

    tdoa_main<<<NBLK, 256>>>(pred, target, mics, (float*)d_out, out_size);
}

// round 15
// speedup vs baseline: 1.3432x; 1.0355x over previous
#include <cuda_runtime.h>
#include <math.h>
#include <float.h>

// Accurate libdevice math (same routines XLA GPU lowers f32 exp/log to).
extern "C" __device__ float __nv_expf(float);
extern "C" __device__ float __nv_logf(float);

// B=64, T=500 -> 32000 (b,t) rows; NLOGIT=13, TR=5, P=6 pairs.
// pred  : (64,500,13,5,6) f32 -> 390 floats per (b,t)
// target: (64,500,5,5,13) f32 -> 325 floats per (b,t)
// mic_locs: (4,3) f32 ; out: [loss, acc] f32
//
// 256 threads = 8 warps, one (b,t) row per warp. Warps retire independently:
// per-warp atomics into 256 buckets + warp counter; last warp finalizes.

#define NBT    32000
#define WPB    8
#define NBLK   (NBT / WPB)   // 4000
#define NBUCK  256

__device__ double             g_bl[NBUCK];    // zero-init; finalizer re-zeroes
__device__ unsigned long long g_bcn[NBUCK];   // (corr<<32) | npred
__device__ unsigned           g_cnt;          // wraps to 0 every full launch

// Lexicographic (itertools) perm index -> digits d[0..4].
__device__ __forceinline__ void perm_digits(int p, int* d) {
    int avail[5] = {0, 1, 2, 3, 4};
    const int fact[4] = {24, 6, 2, 1};
#pragma unroll
    for (int i = 0; i < 4; i++) {
        int q = p / fact[i];
        p -= q * fact[i];
        d[i] = avail[q];
#pragma unroll
        for (int j = 0; j < 4; j++)
            if (j >= q) avail[j] = avail[j + 1];
    }
    d[4] = avail[0];
}

// Fully-unrolled two-chain lazy-division scan over block starts
// pe = pe0 + j*FAC, j in [0, CNT). Exact first-occurrence argmin of
// div(s0,5) in ascending-pe order (div only on strict raw improvement;
// divided-tie keeps the earlier index).
template<int CNT, int FAC>
__device__ __forceinline__ void pscan(
    const unsigned* __restrict__ s_ep2,
    const char* __restrict__ lmB, const char* __restrict__ t13B,
    float a0, int pe0, float& bcst_o, int& bidx_o)
{
    constexpr int HALF = (CNT + 1) / 2;
    float bs0A = FLT_MAX, bcA = FLT_MAX;  int biA = 1 << 20;
    float bs0B = FLT_MAX, bcB = FLT_MAX;  int biB = 1 << 20;
#pragma unroll
    for (int jj = 0; jj < HALF; jj++) {
        {   // chain A (pe ascending)
            int pe = pe0 + jj * FAC;
            unsigned ep = s_ep2[pe];
            float y  = *(const float*)(t13B + (ep & 255u));          // a1+a3
            float a2 = *(const float*)(lmB + ((ep >> 8) & 255u));
            float a4 = *(const float*)(lmB + (ep >> 16));
            float s0 = __fadd_rn(__fadd_rn(__fadd_rn(a0, a4), a2), y);
            if (s0 < bs0A) {
                float cst = __fdiv_rn(s0, 5.0f);
                if (cst < bcA) { bcA = cst; biA = pe; }
                bs0A = s0;
            }
        }
        if (jj + HALF < CNT) {   // chain B (pe ascending), compile-time bound
            int pe = pe0 + (jj + HALF) * FAC;
            unsigned ep = s_ep2[pe];
            float y  = *(const float*)(t13B + (ep & 255u));
            float a2 = *(const float*)(lmB + ((ep >> 8) & 255u));
            float a4 = *(const float*)(lmB + (ep >> 16));
            float s0 = __fadd_rn(__fadd_rn(__fadd_rn(a0, a4), a2), y);
            if (s0 < bs0B) {
                float cst = __fdiv_rn(s0, 5.0f);
                if (cst < bcB) { bcB = cst; biB = pe; }
                bs0B = s0;
            }
        }
    }
    float bc = bcA; int bi = biA;
    if (bcB < bc || (bcB == bc && biB < bi)) { bc = bcB; bi = biB; }
    bcst_o = bc; bidx_o = bi;
}

__global__ __launch_bounds__(256, 8) void tdoa_main(
    const float* __restrict__ pred,
    const float* __restrict__ target,
    const float* __restrict__ mics,
    float* __restrict__ out, int nout)
{
    __shared__ __align__(16) float s_pred[WPB][390];  // cl*30 + track*6 + pair
    // Overlay: phase 1 = s_tgt (325 f); phase 2 = s_lm (150 f) + T13 (150 f).
    __shared__ __align__(16) float s_u[WPB][325];
    __shared__ unsigned char s_cls[WPB][32];   // slot*6 + pair
    __shared__ unsigned char s_pc[WPB][32];    // pair*5 + track
    // Packed byte-offsets per perm: b0=4*(p1*5+p3), b1=4*(10+p2), b2=4*(20+p4)
    __shared__ unsigned s_ep2[128];            // [120..127] = 0
    __shared__ float    s_mics[12];
    __shared__ float    s_gl[WPB][6];          // per-group best cost
    __shared__ int      s_gc[WPB][6];          // per-group correct count

    const int tid  = threadIdx.x;
    const int w    = tid >> 5;
    const int lane = tid & 31;
    const int bt   = blockIdx.x * WPB + w;

    float* s_tgt = s_u[w];           // phase 1
    float* s_lm  = s_u[w];           // phase 2: [0..149]  pair*25 + slot*5 + track
    float* s_t13 = s_u[w] + 150;     // phase 2: [150..299] pair*25 + p1*5 + p3

    // ---- stage inputs + block tables ----
    {
        const float2* pb2 = (const float2*)(pred + (size_t)bt * 390u); // even -> 8B aligned
        float2* sp2 = (float2*)&s_pred[w][0];
#pragma unroll
        for (int i = 0; i < 6; i++) sp2[lane + 32 * i] = pb2[lane + 32 * i];
        if (lane < 3) sp2[192 + lane] = pb2[192 + lane];
        const float* tb = target + (size_t)bt * 325u;
        for (int i = lane; i < 325; i += 32) s_tgt[i] = tb[i];
    }
    if (tid < 128) {
        unsigned ep = 0;
        if (tid < 120) {
            int d[5];
            perm_digits(tid, d);
            ep  = (unsigned)(4 * (d[1] * 5 + d[3]));
            ep |= (unsigned)(4 * (10 + d[2])) << 8;
            ep |= (unsigned)(4 * (20 + d[4])) << 16;
        }
        s_ep2[tid] = ep;
    }
    if (tid < 12) s_mics[tid] = mics[tid];
    __syncthreads();   // tables + own staging visible

    // ---- stable first-<=5 active selection via ballots (f = tr*13 + c) ----
    int f0 = lane, f1 = 32 + lane;
    int tr0 = f0 / 13, c0 = f0 - tr0 * 13;
    int tr1 = f1 / 13, c1 = f1 - tr1 * 13;
    unsigned b0 = __ballot_sync(0xffffffffu, s_tgt[tr0 * 65 + c0] != 0.0f);
    unsigned b1 = __ballot_sync(0xffffffffu, s_tgt[tr1 * 65 + c1] != 0.0f);
    int act64 = (s_tgt[4 * 65 + 12] != 0.0f) ? 1 : 0;   // f = 64
    unsigned long long bits = (unsigned long long)b0 |
                              ((unsigned long long)b1 << 32);
    int total = __popcll(bits) + act64;
    const int v = (total < 5) ? total : 5;

    // fsel on lanes 0..4 (others compute lane-0 copy), broadcast via shfl
    int fsel = 0;
    {
        int sl = (lane < 5) ? lane : 0;
        if (sl < v) {
            if (sl < __popcll(bits)) {
                unsigned long long t = bits;
#pragma unroll
                for (int j = 0; j < 4; j++)
                    if (j < sl) t &= t - 1;
                fsel = __ffsll((long long)t) - 1;
            } else {
                fsel = 64;
            }
        }
    }

    // ---- TDOA class per (slot, pair): 30 lanes ----
    {
        int s  = lane / 6;               // slot (lane<30)
        int pr = lane - s * 6;           // pair
        int f  = __shfl_sync(0xffffffffu, fsel, (s < 5) ? s : 0);
        if (lane < 30) {
            int cls = 0;
            if (s < v) {
                const int pa[6]  = {0, 0, 0, 1, 1, 2};
                const int pbx[6] = {1, 2, 3, 2, 3, 3};
                int tr = f / 13, c = f - tr * 13;
                float dist = s_tgt[tr * 65 + 52 + c];
                float sx = __fmul_rn(s_tgt[tr * 65 + 13 + c], dist);
                float sy = __fmul_rn(s_tgt[tr * 65 + 26 + c], dist);
                float sz = __fmul_rn(s_tgt[tr * 65 + 39 + c], dist);
                int ma = pa[pr], mb = pbx[pr];
                float dxa = __fsub_rn(sx, s_mics[ma * 3 + 0]);
                float dya = __fsub_rn(sy, s_mics[ma * 3 + 1]);
                float dza = __fsub_rn(sz, s_mics[ma * 3 + 2]);
                float dxb = __fsub_rn(sx, s_mics[mb * 3 + 0]);
                float dyb = __fsub_rn(sy, s_mics[mb * 3 + 1]);
                float dzb = __fsub_rn(sz, s_mics[mb * 3 + 2]);
                float qa = __fadd_rn(__fadd_rn(__fmul_rn(dxa, dxa), __fmul_rn(dya, dya)), __fmul_rn(dza, dza));
                float qb = __fadd_rn(__fadd_rn(__fmul_rn(dxb, dxb), __fmul_rn(dyb, dyb)), __fmul_rn(dzb, dzb));
                float tdoa = __fsub_rn(__fsqrt_rn(qa), __fsqrt_rn(qb));
                cls = (int)rintf(__fdiv_rn(__fmul_rn(tdoa, 24000.0f), 343.0f)) + 6;
            }
            s_cls[w][s * 6 + pr] = (unsigned char)cls;
        }
    }
    __syncwarp();

    // ---- log-softmax per (pair, track): 30 lanes, register-lean ----
    if (lane < 30) {
        const int pair  = lane / 5;
        const int track = lane - pair * 5;
        const float* xp = &s_pred[w][track * 6 + pair];   // stride 30

        float mx = -FLT_MAX;
        int   am = 0;
#pragma unroll
        for (int cl = 0; cl < 13; cl++) {
            float x = xp[cl * 30];
            if (x > mx) { mx = x; am = cl; }   // first-occurrence argmax
        }
        // XLA GPU 32-lane column-reduction tree (leaves 13..31 == 0)
        float t0 = __fadd_rn(__nv_expf(__fsub_rn(xp[0],      mx)), __nv_expf(__fsub_rn(xp[8 * 30],  mx)));
        float t1 = __fadd_rn(__nv_expf(__fsub_rn(xp[1 * 30], mx)), __nv_expf(__fsub_rn(xp[9 * 30],  mx)));
        float t2 = __fadd_rn(__nv_expf(__fsub_rn(xp[2 * 30], mx)), __nv_expf(__fsub_rn(xp[10 * 30], mx)));
        float t3 = __fadd_rn(__nv_expf(__fsub_rn(xp[3 * 30], mx)), __nv_expf(__fsub_rn(xp[11 * 30], mx)));
        float t4 = __fadd_rn(__nv_expf(__fsub_rn(xp[4 * 30], mx)), __nv_expf(__fsub_rn(xp[12 * 30], mx)));
        float u0 = __fadd_rn(t0, t4);
        float u1 = __fadd_rn(t1, __nv_expf(__fsub_rn(xp[5 * 30], mx)));
        float u2 = __fadd_rn(t2, __nv_expf(__fsub_rn(xp[6 * 30], mx)));
        float u3 = __fadd_rn(t3, __nv_expf(__fsub_rn(xp[7 * 30], mx)));
        float sm = __fadd_rn(__fadd_rn(u0, u2), __fadd_rn(u1, u3));
        float lse = __nv_logf(sm);
        s_pc[w][pair * 5 + track] = (unsigned char)am;
        float vals[5];
#pragma unroll
        for (int k = 0; k < 5; k++) {
            int idx = (k < v) ? (int)s_cls[w][k * 6 + pair] : 0;
            float xv = xp[idx * 30];
            vals[k] = (k < v) ? __fsub_rn(lse, __fsub_rn(xv, mx)) : 0.0f;
        }
        __syncwarp(0x3fffffffu);   // s_tgt fully dead before lm overwrite
#pragma unroll
        for (int k = 0; k < 5; k++)
            s_lm[pair * 25 + k * 5 + track] = vals[k];
    }
    __syncwarp();

    // ---- build T13[pair][p1][p3] = fadd(lm1[p1], lm3[p3]) (exact tree op) ----
    if (lane < 30) {
        const int pair = lane / 5;
        const int i    = lane - pair * 5;      // p1
        const float* lmp = s_lm + pair * 25;
        float lm1 = lmp[5 + i];
        float* dst = s_t13 + pair * 25 + i * 5;
#pragma unroll
        for (int j = 0; j < 5; j++)
            dst[j] = __fadd_rn(lm1, lmp[15 + j]);
    }
    __syncwarp();

    // ---- perm argmin: group g (5 lanes) owns pair g; lane lig owns the
    // contiguous block pe in [24*lig, 24*lig+24); a0 = lm[lig] loop-invariant.
    // Zero rows (slot k >= v) make perms sharing a v-prefix bitwise-equal
    // (lm > 0 valid, +0 pads), so only block starts pe = pe0 + j*fac are
    // evaluated: cnt = {1,1,4,12,24,24}[v]. v is warp-uniform -> branch into
    // fully-unrolled specializations.
    const int g   = (lane < 30) ? (lane / 5) : 6;
    const int gc6 = (g < 6) ? g : 5;          // clamp for safe addressing
    const int lig = lane - g * 5;             // == p0 for g < 6
    const char* lmB  = (const char*)(s_lm  + gc6 * 25);
    const char* t13B = (const char*)(s_t13 + gc6 * 25);
    const int pe0 = (g < 6) ? lig * 24 : 0;
    const float a0 = ((const float*)lmB)[(g < 6) ? lig : 0];

    float bcst;
    int   bidx;
    if (v >= 4)      pscan<24, 1>(s_ep2, lmB, t13B, a0, pe0, bcst, bidx);
    else if (v == 3) pscan<12, 2>(s_ep2, lmB, t13B, a0, pe0, bcst, bidx);
    else if (v == 2) pscan<4, 6>(s_ep2, lmB, t13B, a0, pe0, bcst, bidx);
    else             pscan<1, 24>(s_ep2, lmB, t13B, a0, pe0, bcst, bidx);

    // group reduce over 5 lanes (offsets 4,2,1, guarded)
#pragma unroll
    for (int off = 4; off; off >>= 1) {
        float ov = __shfl_down_sync(0xffffffffu, bcst, off);
        int   oi = __shfl_down_sync(0xffffffffu, bidx, off);
        if (lig + off < 5 && g < 6) {
            if (ov < bcst || (ov == bcst && oi < bidx)) { bcst = ov; bidx = oi; }
        }
    }

    // group leaders: accuracy count + stash results
    if (g < 6 && lig == 0) {
        int d[5];
        perm_digits(bidx, d);
        int corr = 0;
#pragma unroll
        for (int i = 0; i < 5; i++) {
            int s = d[i];   // tgt_perm[i] = tgt[perm[i]]
            if (s < v && (int)s_pc[w][g * 5 + i] == (int)s_cls[w][s * 6 + g]) corr++;
        }
        s_gl[w][g] = bcst;
        s_gc[w][g] = corr;
    }
    __syncwarp();

    // ---- per-warp direct accumulation (no block sync; warps retire solo) ----
    unsigned t = 0;
    if (lane == 0) {
        double wl = 0.0;
        int    wc = 0;
#pragma unroll
        for (int gg = 0; gg < 6; gg++) {
            wl += (double)s_gl[w][gg];
            wc += s_gc[w][gg];
        }
        int bk = bt & (NBUCK - 1);
        atomicAdd(&g_bl[bk], wl);
        atomicAdd(&g_bcn[bk], ((unsigned long long)wc << 32) |
                              (unsigned long long)(6 * v));
        __threadfence();
        t = atomicInc(&g_cnt, NBT - 1);   // wraps -> clean state per launch
    }
    t = __shfl_sync(0xffffffffu, t, 0);

    if (t == NBT - 1) {
        // last warp: all producers' fences precede their atomicInc
        __threadfence();
        double             L = 0.0;
        unsigned long long CN = 0ull;
#pragma unroll
        for (int r = 0; r < NBUCK / 32; r++) {
            int i = lane + r * 32;
            L  += g_bl[i];
            CN += g_bcn[i];
            g_bl[i]  = 0.0;     // re-zero for next replay
            g_bcn[i] = 0ull;
        }
#pragma unroll
        for (int off = 16; off; off >>= 1) {
            L  += __shfl_down_sync(0xffffffffu, L, off);
            CN += __shfl_down_sync(0xffffffffu, CN, off);
        }
        if (lane == 0) {
            unsigned long long C = CN >> 32;
            unsigned long long N = CN & 0xffffffffull;
            if (nout >= 1) out[0] = (float)(L / 192000.0);
            if (nout >= 2) out[1] = (N > 0) ? (float)((double)C / (double)N) : 0.0f;
        }
    }
}

extern "C" void kernel_launch(void* const* d_in, const int* in_sizes, int n_in,
                              void* d_out, int out_size) {
    const float* pred   = (const float*)d_in[0];
    const float* target = (const float*)d_in[1];
    const float* mics   = (const float*)d_in[2];
    (void)in_sizes; (void)n_in;

    tdoa_main<<<NBLK, 256>>>(pred, target, mics, (float*)d_out, out_size);
}